// round 13
// baseline (speedup 1.0000x reference)
#include <cuda_runtime.h>
#include <cuda_fp16.h>
#include <math.h>
#include <stdint.h>

// ---------------- problem constants ----------------
#define NN 50000
#define EE 400000
#define MBNUM ((NN + 127) / 128)   // 391 M-blocks

// fused weight buffer offsets (elements), layout [NCtot][K] per layer
#define WOFF_L0 0                       // [768][128]
#define WOFF_L1 (WOFF_L0 + 768*128)     // [512][256]
#define WOFF_L2 (WOFF_L1 + 512*256)     // [480][256]
#define WTOT    (WOFF_L2 + 480*256)

// ---------------- scratch (static device globals; 16B-aligned) ----------------
__device__ float g_big0[NN * 768];   // layer0: hs|hd|res
__device__ float g_big1[NN * 512];   // layer1: hs|hd
__device__ float g_big2[NN * 480];   // layer2: hs|hd|res
__device__ float g_xA[NN * 256];
__device__ __align__(256) __half g_xh[NN * 256];
__device__ __align__(256) __half g_hs16[NN * 256];   // fp16 snapshot of hs slice (d64 layers)
__device__ __align__(256) __half g_wh[WTOT];
__device__ float g_b0[768];
__device__ float g_b1[512];
__device__ float g_b2[480];
__device__ int   g_deg[NN];
__device__ int   g_cur[NN];
__device__ int   g_off[NN + 1];
__device__ int   g_ssrc[EE];
__device__ int   g_bsum[64];

// ---------------- helpers (all proven) ----------------
__device__ __forceinline__ uint32_t smem_to_u32(const void* p) {
    uint32_t a;
    asm("{ .reg .u64 t; cvta.to.shared.u64 t, %1; cvt.u32.u64 %0, t; }" : "=r"(a) : "l"(p));
    return a;
}
__device__ __forceinline__ void cp16(uint32_t saddr, const void* gaddr, int sz) {
    asm volatile("cp.async.cg.shared.global [%0], [%1], 16, %2;\n"
                 :: "r"(saddr), "l"(gaddr), "r"(sz));
}
__device__ __forceinline__ void cp_commit() {
    asm volatile("cp.async.commit_group;\n" ::: "memory");
}
template<int N> __device__ __forceinline__ void cp_wait() {
    asm volatile("cp.async.wait_group %0;\n" :: "n"(N) : "memory");
}
__device__ __forceinline__ void ldsm4(uint32_t* r, uint32_t addr) {
    asm volatile("ldmatrix.sync.aligned.m8n8.x4.shared.b16 {%0,%1,%2,%3}, [%4];"
                 : "=r"(r[0]), "=r"(r[1]), "=r"(r[2]), "=r"(r[3]) : "r"(addr));
}
__device__ __forceinline__ void ldsm2(uint32_t* r, uint32_t addr) {
    asm volatile("ldmatrix.sync.aligned.m8n8.x2.shared.b16 {%0,%1}, [%2];"
                 : "=r"(r[0]), "=r"(r[1]) : "r"(addr));
}
__device__ __forceinline__ void mma_f16(float* c, const uint32_t* a, uint32_t b0, uint32_t b1) {
    asm volatile(
        "mma.sync.aligned.m16n8k16.row.col.f32.f16.f16.f32 "
        "{%0,%1,%2,%3}, {%4,%5,%6,%7}, {%8,%9}, {%0,%1,%2,%3};\n"
        : "+f"(c[0]), "+f"(c[1]), "+f"(c[2]), "+f"(c[3])
        : "r"(a[0]), "r"(a[1]), "r"(a[2]), "r"(a[3]), "r"(b0), "r"(b1));
}
// load 4 consecutive halves -> float4 (one 8B load)
__device__ __forceinline__ float4 ldh4(const __half* p) {
    uint2 u = *(const uint2*)p;
    __half2 h0 = *(__half2*)&u.x, h1 = *(__half2*)&u.y;
    float2 f0 = __half22float2(h0), f1 = __half22float2(h1);
    return make_float4(f0.x, f0.y, f1.x, f1.y);
}

// ---------------- CSR build ----------------
__global__ void k_zero(int n) {
    int i = blockIdx.x * 256 + threadIdx.x;
    if (i < n) { g_deg[i] = 0; g_cur[i] = 0; }
}
__global__ void k_hist(const int* __restrict__ dst, int E) {
    int i = blockIdx.x * 256 + threadIdx.x;
    if (i < E) atomicAdd(&g_deg[dst[i]], 1);
}
__global__ void k_scan_reduce(int n) {
    __shared__ int sm[1024];
    int tid = threadIdx.x;
    int i = blockIdx.x * 1024 + tid;
    sm[tid] = (i < n) ? g_deg[i] : 0;
    __syncthreads();
    for (int st = 512; st > 0; st >>= 1) {
        if (tid < st) sm[tid] += sm[tid + st];
        __syncthreads();
    }
    if (tid == 0) g_bsum[blockIdx.x] = sm[0];
}
__global__ void k_scan_bsum(int nb, int n, int E) {
    int run = 0;
    for (int b = 0; b < nb; b++) { int t = g_bsum[b]; g_bsum[b] = run; run += t; }
    g_off[n] = E;
}
__global__ void k_scan_final(int n) {
    __shared__ int sm[1024];
    int tid = threadIdx.x;
    int i = blockIdx.x * 1024 + tid;
    int v = (i < n) ? g_deg[i] : 0;
    sm[tid] = v;
    __syncthreads();
    for (int st = 1; st < 1024; st <<= 1) {
        int t = (tid >= st) ? sm[tid - st] : 0;
        __syncthreads();
        sm[tid] += t;
        __syncthreads();
    }
    if (i < n) g_off[i] = g_bsum[blockIdx.x] + sm[tid] - v;
}
__global__ void k_scatter(const int* __restrict__ src, const int* __restrict__ dst, int E) {
    int i = blockIdx.x * 256 + threadIdx.x;
    if (i < E) {
        int d = dst[i];
        int p = g_off[d] + atomicAdd(&g_cur[d], 1);
        g_ssrc[p] = src[i];
    }
}

// ---------------- prep ----------------
__global__ void k_bias(const float* __restrict__ bs0, const float* __restrict__ bd0,
                       const float* __restrict__ br0, const float* __restrict__ bs1,
                       const float* __restrict__ bd1, const float* __restrict__ bs2,
                       const float* __restrict__ bd2, const float* __restrict__ br2)
{
    int i = blockIdx.x * 256 + threadIdx.x;
    if      (i < 256)  g_b0[i]        = bs0[i];
    else if (i < 512)  g_b0[i]        = bd0[i - 256];
    else if (i < 768)  g_b0[i]        = br0[i - 512];
    else if (i < 1024) g_b1[i - 768]  = bs1[i - 768];
    else if (i < 1280) g_b1[i - 768]  = bd1[i - 1024];
    else if (i < 1440) g_b2[i - 1280] = bs2[i - 1280];
    else if (i < 1600) g_b2[i - 1280] = bd2[i - 1440];
    else if (i < 1760) g_b2[i - 1280] = br2[i - 1600];
}
__global__ void k_xcvt(const float* __restrict__ X, __half* __restrict__ xh, int n)
{
    int i = blockIdx.x * 256 + threadIdx.x;
    if (i < n) xh[i] = __float2half(X[i]);
}
// W[K,NC] -> W'[n][k] = W[k][n] as fp16 at g_wh + woff (row-major [NC][K]).
__global__ void k_wcvt(const float* __restrict__ W, int K, int NC, int woff)
{
    int i = blockIdx.x * 256 + threadIdx.x;
    if (i < K * NC) {
        int n = i / K, k = i - n * K;
        g_wh[woff + i] = __float2half(W[(size_t)k * NC + n]);
    }
}

// ---------------- persistent fp16 GEMM: B staged once, A k-tiles double-buffered ----------------
// C[M,NC] = X @ W + bias; cols < hsW additionally snapshotted to hsAux (fp16, stride hsW).
template<int NFRAG, int KK>
__global__ void __launch_bounds__(512, 1) gemm_pers(
    const __half* __restrict__ A,
    const __half* __restrict__ WBase, int woff,
    const float* __restrict__ bias, float* __restrict__ C,
    __half* __restrict__ hsAux, int hsW,
    int M, int NC)
{
    extern __shared__ char smem[];
    constexpr int BN  = NFRAG * 32;
    constexpr int BK  = 128;
    constexpr int KT  = KK / BK;
    constexpr int ARB = BK * 2 + 16;      // 272
    constexpr int BRB = KK * 2 + 16;      // 272 or 528
    constexpr int szA = 128 * ARB;
    constexpr int NP  = NFRAG / 2;

    const uint32_t sb = smem_to_u32(smem);
    const uint32_t sBp = sb + 2 * szA;
    const int tid  = threadIdx.x;
    const int lane = tid & 31;
    const int wid  = tid >> 5;
    const int wr   = (wid & 3) * 32;
    const int wc   = (wid >> 2) * (NFRAG * 8);
    const int bn   = blockIdx.y * BN;
    const int g    = lane >> 2;
    const int tg   = lane & 3;
    const int m8   = lane >> 3;
    const int r8   = lane & 7;
    const int aRow = (m8 & 1) * 8 + r8;
    const int aK   = (m8 >> 1) * 16;
    const int bRow = (m8 >> 1) * 8 + r8;
    const int bK   = (m8 & 1) * 16;
    const __half* __restrict__ B = WBase + woff;

    // ---- stage B panel (once) ----
    for (int i = tid; i < BN * (KK / 8); i += 512) {
        int row = i / (KK / 8), c = i % (KK / 8);
        cp16(sBp + row * BRB + c * 16, B + (size_t)(bn + row) * KK + c * 8, 16);
    }
    auto stageA = [&](uint32_t buf, int mb, int kt) {
        int bm = mb * 128;
        for (int i = tid; i < 2048; i += 512) {
            int row = i >> 4, c = i & 15;
            uint32_t sa = buf + row * ARB + c * 16;
            size_t go = (size_t)(bm + row) * KK + kt * BK + c * 8;
            cp16(sa, A + go, (bm + row < M) ? 16 : 0);
        }
    };
    stageA(sb, blockIdx.x, 0);
    cp_commit();

    int nM = 0;
    for (int m = blockIdx.x; m < MBNUM; m += gridDim.x) nM++;
    const int nT = nM * KT;

    float acc[2][NFRAG][4];
#pragma unroll
    for (int i = 0; i < 2; i++)
#pragma unroll
        for (int j = 0; j < NFRAG; j++)
#pragma unroll
            for (int k = 0; k < 4; k++) acc[i][j][k] = 0.f;

    for (int t = 0; t < nT; t++) {
        int nxt = t + 1;
        if (nxt < nT) {
            int mb = blockIdx.x + (nxt / KT) * gridDim.x;
            stageA(sb + (nxt & 1) * szA, mb, nxt % KT);
            cp_commit();
            cp_wait<1>();
        } else {
            cp_wait<0>();
        }
        __syncthreads();

        const uint32_t sA = sb + (t & 1) * szA;
        const int ktile = t % KT;
#pragma unroll
        for (int kc = 0; kc < BK / 16; kc++) {
            const int kbA = kc * 32;
            const int kbB = ktile * (BK * 2) + kc * 32;
            uint32_t a[2][4];
#pragma unroll
            for (int fr = 0; fr < 2; fr++) {
                uint32_t off = (uint32_t)(wr + fr * 16 + aRow) * ARB + kbA + aK;
                ldsm4(a[fr], sA + off);
            }
            uint32_t b[NFRAG][2];
#pragma unroll
            for (int p = 0; p < NP; p++) {
                uint32_t off = (uint32_t)(wc + p * 16 + bRow) * BRB + kbB + bK;
                uint32_t tt[4];
                ldsm4(tt, sBp + off);
                b[2*p][0] = tt[0]; b[2*p][1] = tt[1]; b[2*p+1][0] = tt[2]; b[2*p+1][1] = tt[3];
            }
            if (NFRAG & 1) {
                uint32_t off = (uint32_t)(wc + (NFRAG - 1) * 8 + r8) * BRB + kbB + (m8 & 1) * 16;
                uint32_t tt[2];
                ldsm2(tt, sBp + off);
                b[NFRAG-1][0] = tt[0]; b[NFRAG-1][1] = tt[1];
            }
#pragma unroll
            for (int fc = 0; fc < NFRAG; fc++)
#pragma unroll
                for (int fr = 0; fr < 2; fr++)
                    mma_f16(acc[fr][fc], a[fr], b[fc][0], b[fc][1]);
        }

        if (ktile == KT - 1) {
            int bm = (blockIdx.x + (t / KT) * gridDim.x) * 128;
#pragma unroll
            for (int fr = 0; fr < 2; fr++) {
                int r0 = bm + wr + fr * 16 + g;
#pragma unroll
                for (int fc = 0; fc < NFRAG; fc++) {
                    int c = bn + wc + fc * 8 + tg * 2;
                    float2 bb = *(const float2*)(bias + c);
                    float2 o0 = make_float2(acc[fr][fc][0] + bb.x, acc[fr][fc][1] + bb.y);
                    float2 o1 = make_float2(acc[fr][fc][2] + bb.x, acc[fr][fc][3] + bb.y);
                    if (r0 < M) {
                        *(float2*)(C + (size_t)r0 * NC + c) = o0;
                        if (hsAux && c < hsW)
                            *(__half2*)(hsAux + (size_t)r0 * hsW + c) = __floats2half2_rn(o0.x, o0.y);
                    }
                    if (r0 + 8 < M) {
                        *(float2*)(C + (size_t)(r0 + 8) * NC + c) = o1;
                        if (hsAux && c < hsW)
                            *(__half2*)(hsAux + (size_t)(r0 + 8) * hsW + c) = __floats2half2_rn(o1.x, o1.y);
                    }
#pragma unroll
                    for (int k = 0; k < 4; k++) acc[fr][fc][k] = 0.f;
                }
            }
        }
        __syncthreads();
    }
}

// ---------------- edge kernels ----------------
__device__ __forceinline__ float lrelu(float t) { return t > 0.f ? t : 0.2f * t; }
__device__ __forceinline__ float lrdot(float4 h, float4 d, float4 a) {
    return lrelu(h.x + d.x) * a.x + lrelu(h.y + d.y) * a.y +
           lrelu(h.z + d.z) * a.z + lrelu(h.w + d.w) * a.w;
}

// d64: gathers hs rows from fp16 snapshot (stride 256), computes fp32.
__global__ void __launch_bounds__(256) gat_edge_d64(
    const __half* __restrict__ hs16,
    const float* __restrict__ hdB, int hdS,
    const float* __restrict__ attn,
    const float* __restrict__ resB, int resS,
    float* __restrict__ xout, __half* __restrict__ xh, int N)
{
    int w = (blockIdx.x * blockDim.x + threadIdx.x) >> 5;
    if (w >= N) return;
    int lane = threadIdx.x & 31;
    int i1 = 4 * lane, i2 = 128 + 4 * lane;
    float4 a1 = *(const float4*)(attn + i1);
    float4 a2 = *(const float4*)(attn + i2);
    const float* hdp = hdB + (size_t)w * hdS;
    float4 d1 = *(const float4*)(hdp + i1);
    float4 d2 = *(const float4*)(hdp + i2);
    float s1 = 0.f, s2 = 0.f;
    float4 c1 = make_float4(0.f, 0.f, 0.f, 0.f);
    float4 c2 = make_float4(0.f, 0.f, 0.f, 0.f);
    int e = g_off[w], e1 = g_off[w + 1];
    float4 xa1, xa2, xb1, xb2;
    if (e < e1) {
        const __half* hp = hs16 + (size_t)g_ssrc[e] * 256;
        xa1 = ldh4(hp + i1); xa2 = ldh4(hp + i2);
    }
    if (e + 1 < e1) {
        const __half* hp = hs16 + (size_t)g_ssrc[e + 1] * 256;
        xb1 = ldh4(hp + i1); xb2 = ldh4(hp + i2);
    }
    while (e < e1) {
        float4 u1 = xa1, u2 = xa2, v1 = xb1, v2 = xb2;
        bool two = (e + 1 < e1);
        if (e + 2 < e1) {
            const __half* hp = hs16 + (size_t)g_ssrc[e + 2] * 256;
            xa1 = ldh4(hp + i1); xa2 = ldh4(hp + i2);
        }
        if (e + 3 < e1) {
            const __half* hp = hs16 + (size_t)g_ssrc[e + 3] * 256;
            xb1 = ldh4(hp + i1); xb2 = ldh4(hp + i2);
        }
        float pa1 = lrdot(u1, d1, a1), pa2 = lrdot(u2, d2, a2);
        float pb1 = 0.f, pb2 = 0.f;
        if (two) { pb1 = lrdot(v1, d1, a1); pb2 = lrdot(v2, d2, a2); }
#pragma unroll
        for (int o = 8; o; o >>= 1) {
            pa1 += __shfl_xor_sync(0xffffffffu, pa1, o);
            pa2 += __shfl_xor_sync(0xffffffffu, pa2, o);
            pb1 += __shfl_xor_sync(0xffffffffu, pb1, o);
            pb2 += __shfl_xor_sync(0xffffffffu, pb2, o);
        }
        float wa1 = __expf(pa1), wa2 = __expf(pa2);
        s1 += wa1; s2 += wa2;
        c1.x += wa1 * u1.x; c1.y += wa1 * u1.y; c1.z += wa1 * u1.z; c1.w += wa1 * u1.w;
        c2.x += wa2 * u2.x; c2.y += wa2 * u2.y; c2.z += wa2 * u2.z; c2.w += wa2 * u2.w;
        if (two) {
            float wb1 = __expf(pb1), wb2 = __expf(pb2);
            s1 += wb1; s2 += wb2;
            c1.x += wb1 * v1.x; c1.y += wb1 * v1.y; c1.z += wb1 * v1.z; c1.w += wb1 * v1.w;
            c2.x += wb2 * v2.x; c2.y += wb2 * v2.y; c2.z += wb2 * v2.z; c2.w += wb2 * v2.w;
        }
        e += 2;
    }
    float inv1 = (s1 > 0.f) ? 1.f / s1 : 0.f;
    float inv2 = (s2 > 0.f) ? 1.f / s2 : 0.f;
    const float* rp = resB + (size_t)w * resS;
    float4 r1 = *(const float4*)(rp + i1);
    float4 r2 = *(const float4*)(rp + i2);
    float o1[4], o2[4];
    o1[0] = c1.x * inv1 + r1.x; o1[1] = c1.y * inv1 + r1.y;
    o1[2] = c1.z * inv1 + r1.z; o1[3] = c1.w * inv1 + r1.w;
    o2[0] = c2.x * inv2 + r2.x; o2[1] = c2.y * inv2 + r2.y;
    o2[2] = c2.z * inv2 + r2.z; o2[3] = c2.w * inv2 + r2.w;
    size_t nb = (size_t)w * 256;
    if (xout) {
        *(float4*)(xout + nb + i1) = make_float4(o1[0], o1[1], o1[2], o1[3]);
        *(float4*)(xout + nb + i2) = make_float4(o2[0], o2[1], o2[2], o2[3]);
    }
    __half2* xh2 = (__half2*)(xh + nb);
#pragma unroll
    for (int j = 0; j < 2; j++) {
        xh2[(i1 >> 1) + j] = __floats2half2_rn(o1[2*j], o1[2*j+1]);
        xh2[(i2 >> 1) + j] = __floats2half2_rn(o2[2*j], o2[2*j+1]);
    }
}

__global__ void __launch_bounds__(256) gat_edge_d40(
    const float* __restrict__ hsB, int hsS,
    const float* __restrict__ hdB, int hdS,
    const float* __restrict__ attn,
    const float* __restrict__ resB, int resS,
    float* __restrict__ out, int N)
{
    int w = (blockIdx.x * blockDim.x + threadIdx.x) >> 5;
    if (w >= N) return;
    int lane = threadIdx.x & 31;
    int h = lane >> 3;
    int d0 = (lane & 7) * 5;
    int idx = h * 40 + d0;
    float a[5], dv[5];
    const float* hdp = hdB + (size_t)w * hdS + idx;
#pragma unroll
    for (int j = 0; j < 5; j++) { a[j] = attn[idx + j]; dv[j] = hdp[j]; }
    float s = 0.f;
    float acc[5] = {0.f, 0.f, 0.f, 0.f, 0.f};
    int e = g_off[w], e1 = g_off[w + 1];
    float pfa[5], pfb[5];
    if (e < e1) {
        const float* hp = hsB + (size_t)g_ssrc[e] * hsS + idx;
#pragma unroll
        for (int j = 0; j < 5; j++) pfa[j] = hp[j];
    }
    if (e + 1 < e1) {
        const float* hp = hsB + (size_t)g_ssrc[e + 1] * hsS + idx;
#pragma unroll
        for (int j = 0; j < 5; j++) pfb[j] = hp[j];
    }
    while (e < e1) {
        float ua[5], ub[5];
#pragma unroll
        for (int j = 0; j < 5; j++) { ua[j] = pfa[j]; ub[j] = pfb[j]; }
        bool two = (e + 1 < e1);
        if (e + 2 < e1) {
            const float* hp = hsB + (size_t)g_ssrc[e + 2] * hsS + idx;
#pragma unroll
            for (int j = 0; j < 5; j++) pfa[j] = hp[j];
        }
        if (e + 3 < e1) {
            const float* hp = hsB + (size_t)g_ssrc[e + 3] * hsS + idx;
#pragma unroll
            for (int j = 0; j < 5; j++) pfb[j] = hp[j];
        }
        float qa = 0.f, qb = 0.f;
#pragma unroll
        for (int j = 0; j < 5; j++) qa += lrelu(ua[j] + dv[j]) * a[j];
        if (two) {
#pragma unroll
            for (int j = 0; j < 5; j++) qb += lrelu(ub[j] + dv[j]) * a[j];
        }
#pragma unroll
        for (int o = 4; o; o >>= 1) {
            qa += __shfl_xor_sync(0xffffffffu, qa, o);
            qb += __shfl_xor_sync(0xffffffffu, qb, o);
        }
        float wa = __expf(qa);
        s += wa;
#pragma unroll
        for (int j = 0; j < 5; j++) acc[j] += wa * ua[j];
        if (two) {
            float wb = __expf(qb);
            s += wb;
#pragma unroll
            for (int j = 0; j < 5; j++) acc[j] += wb * ub[j];
        }
        e += 2;
    }
    float inv = (s > 0.f) ? 1.f / s : 0.f;
    const float* rp = resB + (size_t)w * resS + idx;
    float v[5];
#pragma unroll
    for (int j = 0; j < 5; j++) v[j] = acc[j] * inv + rp[j];
#pragma unroll
    for (int j = 0; j < 5; j++) {
        v[j] += __shfl_xor_sync(0xffffffffu, v[j], 8);
        v[j] += __shfl_xor_sync(0xffffffffu, v[j], 16);
    }
    if (lane < 8) {
#pragma unroll
        for (int j = 0; j < 5; j++) out[(size_t)w * 40 + d0 + j] = 0.25f * v[j];
    }
}

// ---------------- launch ----------------
#define SMEM_L0 (2 * 128 * 272 + 256 * 272)   // 139264
#define SMEM_L1 (2 * 128 * 272 + 256 * 528)   // 204800
#define SMEM_L2 (2 * 128 * 272 + 160 * 528)   // 154112

extern "C" void kernel_launch(void* const* d_in, const int* in_sizes, int n_in,
                              void* d_out, int out_size)
{
    const float* x0  = (const float*)d_in[0];
    const int*   src = (const int*)d_in[1];
    const int*   dst = (const int*)d_in[2];
    const float* ws0 = (const float*)d_in[3];
    const float* bs0 = (const float*)d_in[4];
    const float* wd0 = (const float*)d_in[5];
    const float* bd0 = (const float*)d_in[6];
    const float* at0 = (const float*)d_in[7];
    const float* wr0 = (const float*)d_in[8];
    const float* br0 = (const float*)d_in[9];
    const float* ws1 = (const float*)d_in[10];
    const float* bs1 = (const float*)d_in[11];
    const float* wd1 = (const float*)d_in[12];
    const float* bd1 = (const float*)d_in[13];
    const float* at1 = (const float*)d_in[14];
    const float* ws2 = (const float*)d_in[15];
    const float* bs2 = (const float*)d_in[16];
    const float* wd2 = (const float*)d_in[17];
    const float* bd2 = (const float*)d_in[18];
    const float* at2 = (const float*)d_in[19];
    const float* wr2 = (const float*)d_in[20];
    const float* br2 = (const float*)d_in[21];
    float* out = (float*)d_out;

    const int N = NN, E = EE;

    float *big0, *big1, *big2, *xA, *b0, *b1, *b2;
    __half *xh, *wh, *hs16;
    cudaGetSymbolAddress((void**)&big0, g_big0);
    cudaGetSymbolAddress((void**)&big1, g_big1);
    cudaGetSymbolAddress((void**)&big2, g_big2);
    cudaGetSymbolAddress((void**)&xA,   g_xA);
    cudaGetSymbolAddress((void**)&xh,   g_xh);
    cudaGetSymbolAddress((void**)&wh,   g_wh);
    cudaGetSymbolAddress((void**)&hs16, g_hs16);
    cudaGetSymbolAddress((void**)&b0,   g_b0);
    cudaGetSymbolAddress((void**)&b1,   g_b1);
    cudaGetSymbolAddress((void**)&b2,   g_b2);

    cudaFuncSetAttribute(gemm_pers<8,128>, cudaFuncAttributeMaxDynamicSharedMemorySize, SMEM_L0);
    cudaFuncSetAttribute(gemm_pers<8,256>, cudaFuncAttributeMaxDynamicSharedMemorySize, SMEM_L1);
    cudaFuncSetAttribute(gemm_pers<5,256>, cudaFuncAttributeMaxDynamicSharedMemorySize, SMEM_L2);

    const int ewarps = (N * 32 + 255) / 256;

    // ---- prep + fused layer0 GEMM ----
    k_bias<<<(1760 + 255) / 256, 256>>>(bs0, bd0, br0, bs1, bd1, bs2, bd2, br2);
    k_xcvt<<<(N * 128 + 255) / 256, 256>>>(x0, xh, N * 128);
    k_wcvt<<<(128 * 256 + 255) / 256, 256>>>(ws0, 128, 256, WOFF_L0);
    k_wcvt<<<(128 * 256 + 255) / 256, 256>>>(wd0, 128, 256, WOFF_L0 + 256 * 128);
    k_wcvt<<<(128 * 256 + 255) / 256, 256>>>(wr0, 128, 256, WOFF_L0 + 512 * 128);
    gemm_pers<8,128><<<dim3(49, 3), 512, SMEM_L0>>>(xh, wh, WOFF_L0, b0, big0, hs16, 256, N, 768);

    // ---- CSR by dst ----
    k_zero<<<(N + 255) / 256, 256>>>(N);
    k_hist<<<(E + 255) / 256, 256>>>(dst, E);
    int NB = (N + 1023) / 1024;
    k_scan_reduce<<<NB, 1024>>>(N);
    k_scan_bsum<<<1, 1>>>(NB, N, E);
    k_scan_final<<<NB, 1024>>>(N);
    k_scatter<<<(E + 255) / 256, 256>>>(src, dst, E);

    gat_edge_d64<<<ewarps, 256>>>(hs16, big0 + 256, 768, at0,
                                  big0 + 512, 768, xA, xh, N);

    // ---- layer 1: fused hs|hd, identity residual (xA) ----
    k_wcvt<<<(256 * 256 + 255) / 256, 256>>>(ws1, 256, 256, WOFF_L1);
    k_wcvt<<<(256 * 256 + 255) / 256, 256>>>(wd1, 256, 256, WOFF_L1 + 256 * 256);
    gemm_pers<8,256><<<dim3(74, 2), 512, SMEM_L1>>>(xh, wh, WOFF_L1, b1, big1, hs16, 256, N, 512);
    gat_edge_d64<<<ewarps, 256>>>(hs16, big1 + 256, 512, at1,
                                  xA, 256, nullptr, xh, N);

    // ---- layer 2: fused hs|hd|res (BN=160), fused head-mean -> out ----
    k_wcvt<<<(256 * 160 + 255) / 256, 256>>>(ws2, 256, 160, WOFF_L2);
    k_wcvt<<<(256 * 160 + 255) / 256, 256>>>(wd2, 256, 160, WOFF_L2 + 160 * 256);
    k_wcvt<<<(256 * 160 + 255) / 256, 256>>>(wr2, 256, 160, WOFF_L2 + 320 * 256);
    gemm_pers<5,256><<<dim3(49, 3), 512, SMEM_L2>>>(xh, wh, WOFF_L2, b2, big2, nullptr, 0, N, 480);
    gat_edge_d40<<<ewarps, 256>>>(big2, 480, big2 + 160, 480, at2,
                                  big2 + 320, 480, out, N);
}

// round 14
// speedup vs baseline: 1.0438x; 1.0438x over previous
#include <cuda_runtime.h>
#include <cuda_fp16.h>
#include <math.h>
#include <stdint.h>

// ---------------- problem constants ----------------
#define NN 50000
#define EE 400000
#define MBNUM ((NN + 127) / 128)   // 391 M-blocks

// fused weight buffer offsets (elements), layout [NCtot][K] per layer
#define WOFF_L0 0                       // [768][128]
#define WOFF_L1 (WOFF_L0 + 768*128)     // [512][256]
#define WOFF_L2 (WOFF_L1 + 512*256)     // [480][256]
#define WTOT    (WOFF_L2 + 480*256)

// ---------------- scratch (static device globals; 16B-aligned) ----------------
__device__ float g_big0[NN * 768];   // layer0: hs|hd|res
__device__ float g_big1[NN * 512];   // layer1: hs|hd
__device__ float g_big2[NN * 480];   // layer2: hs|hd|res
__device__ float g_xA[NN * 256];
__device__ __align__(256) __half g_xh[NN * 256];
__device__ __align__(256) __half g_hs16[NN * 256];   // compact fp16 copy of hs slice
__device__ __align__(256) __half g_wh[WTOT];
__device__ float g_b0[768];
__device__ float g_b1[512];
__device__ float g_b2[480];
__device__ int   g_deg[NN];
__device__ int   g_cur[NN];
__device__ int   g_off[NN + 1];
__device__ int   g_ssrc[EE];
__device__ int   g_bsum[64];

// ---------------- helpers (all proven) ----------------
__device__ __forceinline__ uint32_t smem_to_u32(const void* p) {
    uint32_t a;
    asm("{ .reg .u64 t; cvta.to.shared.u64 t, %1; cvt.u32.u64 %0, t; }" : "=r"(a) : "l"(p));
    return a;
}
__device__ __forceinline__ void cp16(uint32_t saddr, const void* gaddr, int sz) {
    asm volatile("cp.async.cg.shared.global [%0], [%1], 16, %2;\n"
                 :: "r"(saddr), "l"(gaddr), "r"(sz));
}
__device__ __forceinline__ void cp_commit() {
    asm volatile("cp.async.commit_group;\n" ::: "memory");
}
template<int N> __device__ __forceinline__ void cp_wait() {
    asm volatile("cp.async.wait_group %0;\n" :: "n"(N) : "memory");
}
__device__ __forceinline__ void ldsm4(uint32_t* r, uint32_t addr) {
    asm volatile("ldmatrix.sync.aligned.m8n8.x4.shared.b16 {%0,%1,%2,%3}, [%4];"
                 : "=r"(r[0]), "=r"(r[1]), "=r"(r[2]), "=r"(r[3]) : "r"(addr));
}
__device__ __forceinline__ void ldsm2(uint32_t* r, uint32_t addr) {
    asm volatile("ldmatrix.sync.aligned.m8n8.x2.shared.b16 {%0,%1}, [%2];"
                 : "=r"(r[0]), "=r"(r[1]) : "r"(addr));
}
__device__ __forceinline__ void mma_f16(float* c, const uint32_t* a, uint32_t b0, uint32_t b1) {
    asm volatile(
        "mma.sync.aligned.m16n8k16.row.col.f32.f16.f16.f32 "
        "{%0,%1,%2,%3}, {%4,%5,%6,%7}, {%8,%9}, {%0,%1,%2,%3};\n"
        : "+f"(c[0]), "+f"(c[1]), "+f"(c[2]), "+f"(c[3])
        : "r"(a[0]), "r"(a[1]), "r"(a[2]), "r"(a[3]), "r"(b0), "r"(b1));
}
// load 4 consecutive halves -> float4 (one 8B load)
__device__ __forceinline__ float4 ldh4(const __half* p) {
    uint2 u = *(const uint2*)p;
    __half2 h0 = *(__half2*)&u.x, h1 = *(__half2*)&u.y;
    float2 f0 = __half22float2(h0), f1 = __half22float2(h1);
    return make_float4(f0.x, f0.y, f1.x, f1.y);
}

// ---------------- CSR build ----------------
__global__ void k_zero(int n) {
    int i = blockIdx.x * 256 + threadIdx.x;
    if (i < n) { g_deg[i] = 0; g_cur[i] = 0; }
}
__global__ void k_hist(const int* __restrict__ dst, int E) {
    int i = blockIdx.x * 256 + threadIdx.x;
    if (i < E) atomicAdd(&g_deg[dst[i]], 1);
}
__global__ void k_scan_reduce(int n) {
    __shared__ int sm[1024];
    int tid = threadIdx.x;
    int i = blockIdx.x * 1024 + tid;
    sm[tid] = (i < n) ? g_deg[i] : 0;
    __syncthreads();
    for (int st = 512; st > 0; st >>= 1) {
        if (tid < st) sm[tid] += sm[tid + st];
        __syncthreads();
    }
    if (tid == 0) g_bsum[blockIdx.x] = sm[0];
}
__global__ void k_scan_bsum(int nb, int n, int E) {
    int run = 0;
    for (int b = 0; b < nb; b++) { int t = g_bsum[b]; g_bsum[b] = run; run += t; }
    g_off[n] = E;
}
__global__ void k_scan_final(int n) {
    __shared__ int sm[1024];
    int tid = threadIdx.x;
    int i = blockIdx.x * 1024 + tid;
    int v = (i < n) ? g_deg[i] : 0;
    sm[tid] = v;
    __syncthreads();
    for (int st = 1; st < 1024; st <<= 1) {
        int t = (tid >= st) ? sm[tid - st] : 0;
        __syncthreads();
        sm[tid] += t;
        __syncthreads();
    }
    if (i < n) g_off[i] = g_bsum[blockIdx.x] + sm[tid] - v;
}
__global__ void k_scatter(const int* __restrict__ src, const int* __restrict__ dst, int E) {
    int i = blockIdx.x * 256 + threadIdx.x;
    if (i < E) {
        int d = dst[i];
        int p = g_off[d] + atomicAdd(&g_cur[d], 1);
        g_ssrc[p] = src[i];
    }
}

// ---------------- prep ----------------
__global__ void k_bias(const float* __restrict__ bs0, const float* __restrict__ bd0,
                       const float* __restrict__ br0, const float* __restrict__ bs1,
                       const float* __restrict__ bd1, const float* __restrict__ bs2,
                       const float* __restrict__ bd2, const float* __restrict__ br2)
{
    int i = blockIdx.x * 256 + threadIdx.x;
    if      (i < 256)  g_b0[i]        = bs0[i];
    else if (i < 512)  g_b0[i]        = bd0[i - 256];
    else if (i < 768)  g_b0[i]        = br0[i - 512];
    else if (i < 1024) g_b1[i - 768]  = bs1[i - 768];
    else if (i < 1280) g_b1[i - 768]  = bd1[i - 1024];
    else if (i < 1440) g_b2[i - 1280] = bs2[i - 1280];
    else if (i < 1600) g_b2[i - 1280] = bd2[i - 1440];
    else if (i < 1760) g_b2[i - 1280] = br2[i - 1600];
}
__global__ void k_xcvt(const float* __restrict__ X, __half* __restrict__ xh, int n)
{
    int i = blockIdx.x * 256 + threadIdx.x;
    if (i < n) xh[i] = __float2half(X[i]);
}
// W[K,NC] -> W'[n][k] = W[k][n] as fp16 at g_wh + woff (row-major [NC][K]).
__global__ void k_wcvt(const float* __restrict__ W, int K, int NC, int woff)
{
    int i = blockIdx.x * 256 + threadIdx.x;
    if (i < K * NC) {
        int n = i / K, k = i - n * K;
        g_wh[woff + i] = __float2half(W[(size_t)k * NC + n]);
    }
}
// hs slice (cols [0,256) of big, stride NC) -> compact fp16 [N][256].
// thread handles 4 elements (one float4 read, one half2x2 write).
__global__ void k_hcvt(const float* __restrict__ big, int NC, __half* __restrict__ hs16, int N)
{
    int i = blockIdx.x * 256 + threadIdx.x;   // i indexes groups of 4
    if (i < N * 64) {
        int row = i >> 6, c4 = (i & 63) * 4;
        float4 v = *(const float4*)(big + (size_t)row * NC + c4);
        __half2* o = (__half2*)(hs16 + (size_t)row * 256 + c4);
        o[0] = __floats2half2_rn(v.x, v.y);
        o[1] = __floats2half2_rn(v.z, v.w);
    }
}

// ---------------- persistent fp16 GEMM (round-12 version, untouched) ----------------
template<int NFRAG, int KK>
__global__ void __launch_bounds__(512, 1) gemm_pers(
    const __half* __restrict__ A,
    const __half* __restrict__ WBase, int woff,
    const float* __restrict__ bias, float* __restrict__ C,
    int M, int NC)
{
    extern __shared__ char smem[];
    constexpr int BN  = NFRAG * 32;
    constexpr int BK  = 128;
    constexpr int KT  = KK / BK;
    constexpr int ARB = BK * 2 + 16;      // 272
    constexpr int BRB = KK * 2 + 16;      // 272 or 528
    constexpr int szA = 128 * ARB;
    constexpr int NP  = NFRAG / 2;

    const uint32_t sb = smem_to_u32(smem);
    const uint32_t sBp = sb + 2 * szA;
    const int tid  = threadIdx.x;
    const int lane = tid & 31;
    const int wid  = tid >> 5;
    const int wr   = (wid & 3) * 32;
    const int wc   = (wid >> 2) * (NFRAG * 8);
    const int bn   = blockIdx.y * BN;
    const int g    = lane >> 2;
    const int tg   = lane & 3;
    const int m8   = lane >> 3;
    const int r8   = lane & 7;
    const int aRow = (m8 & 1) * 8 + r8;
    const int aK   = (m8 >> 1) * 16;
    const int bRow = (m8 >> 1) * 8 + r8;
    const int bK   = (m8 & 1) * 16;
    const __half* __restrict__ B = WBase + woff;

    for (int i = tid; i < BN * (KK / 8); i += 512) {
        int row = i / (KK / 8), c = i % (KK / 8);
        cp16(sBp + row * BRB + c * 16, B + (size_t)(bn + row) * KK + c * 8, 16);
    }
    auto stageA = [&](uint32_t buf, int mb, int kt) {
        int bm = mb * 128;
        for (int i = tid; i < 2048; i += 512) {
            int row = i >> 4, c = i & 15;
            uint32_t sa = buf + row * ARB + c * 16;
            size_t go = (size_t)(bm + row) * KK + kt * BK + c * 8;
            cp16(sa, A + go, (bm + row < M) ? 16 : 0);
        }
    };
    stageA(sb, blockIdx.x, 0);
    cp_commit();

    int nM = 0;
    for (int m = blockIdx.x; m < MBNUM; m += gridDim.x) nM++;
    const int nT = nM * KT;

    float acc[2][NFRAG][4];
#pragma unroll
    for (int i = 0; i < 2; i++)
#pragma unroll
        for (int j = 0; j < NFRAG; j++)
#pragma unroll
            for (int k = 0; k < 4; k++) acc[i][j][k] = 0.f;

    for (int t = 0; t < nT; t++) {
        int nxt = t + 1;
        if (nxt < nT) {
            int mb = blockIdx.x + (nxt / KT) * gridDim.x;
            stageA(sb + (nxt & 1) * szA, mb, nxt % KT);
            cp_commit();
            cp_wait<1>();
        } else {
            cp_wait<0>();
        }
        __syncthreads();

        const uint32_t sA = sb + (t & 1) * szA;
        const int ktile = t % KT;
#pragma unroll
        for (int kc = 0; kc < BK / 16; kc++) {
            const int kbA = kc * 32;
            const int kbB = ktile * (BK * 2) + kc * 32;
            uint32_t a[2][4];
#pragma unroll
            for (int fr = 0; fr < 2; fr++) {
                uint32_t off = (uint32_t)(wr + fr * 16 + aRow) * ARB + kbA + aK;
                ldsm4(a[fr], sA + off);
            }
            uint32_t b[NFRAG][2];
#pragma unroll
            for (int p = 0; p < NP; p++) {
                uint32_t off = (uint32_t)(wc + p * 16 + bRow) * BRB + kbB + bK;
                uint32_t tt[4];
                ldsm4(tt, sBp + off);
                b[2*p][0] = tt[0]; b[2*p][1] = tt[1]; b[2*p+1][0] = tt[2]; b[2*p+1][1] = tt[3];
            }
            if (NFRAG & 1) {
                uint32_t off = (uint32_t)(wc + (NFRAG - 1) * 8 + r8) * BRB + kbB + (m8 & 1) * 16;
                uint32_t tt[2];
                ldsm2(tt, sBp + off);
                b[NFRAG-1][0] = tt[0]; b[NFRAG-1][1] = tt[1];
            }
#pragma unroll
            for (int fc = 0; fc < NFRAG; fc++)
#pragma unroll
                for (int fr = 0; fr < 2; fr++)
                    mma_f16(acc[fr][fc], a[fr], b[fc][0], b[fc][1]);
        }

        if (ktile == KT - 1) {
            int bm = (blockIdx.x + (t / KT) * gridDim.x) * 128;
#pragma unroll
            for (int fr = 0; fr < 2; fr++) {
                int r0 = bm + wr + fr * 16 + g;
#pragma unroll
                for (int fc = 0; fc < NFRAG; fc++) {
                    int c = bn + wc + fc * 8 + tg * 2;
                    float2 bb = *(const float2*)(bias + c);
                    if (r0 < M) {
                        float2 o = make_float2(acc[fr][fc][0] + bb.x, acc[fr][fc][1] + bb.y);
                        *(float2*)(C + (size_t)r0 * NC + c) = o;
                    }
                    if (r0 + 8 < M) {
                        float2 o = make_float2(acc[fr][fc][2] + bb.x, acc[fr][fc][3] + bb.y);
                        *(float2*)(C + (size_t)(r0 + 8) * NC + c) = o;
                    }
#pragma unroll
                    for (int k = 0; k < 4; k++) acc[fr][fc][k] = 0.f;
                }
            }
        }
        __syncthreads();
    }
}

// ---------------- edge kernels ----------------
__device__ __forceinline__ float lrelu(float t) { return t > 0.f ? t : 0.2f * t; }
__device__ __forceinline__ float lrdot(float4 h, float4 d, float4 a) {
    return lrelu(h.x + d.x) * a.x + lrelu(h.y + d.y) * a.y +
           lrelu(h.z + d.z) * a.z + lrelu(h.w + d.w) * a.w;
}

// d64: gathers hs rows from compact fp16 copy (stride 256), computes fp32.
__global__ void __launch_bounds__(256) gat_edge_d64(
    const __half* __restrict__ hs16,
    const float* __restrict__ hdB, int hdS,
    const float* __restrict__ attn,
    const float* __restrict__ resB, int resS,
    float* __restrict__ xout, __half* __restrict__ xh, int N)
{
    int w = (blockIdx.x * blockDim.x + threadIdx.x) >> 5;
    if (w >= N) return;
    int lane = threadIdx.x & 31;
    int i1 = 4 * lane, i2 = 128 + 4 * lane;
    float4 a1 = *(const float4*)(attn + i1);
    float4 a2 = *(const float4*)(attn + i2);
    const float* hdp = hdB + (size_t)w * hdS;
    float4 d1 = *(const float4*)(hdp + i1);
    float4 d2 = *(const float4*)(hdp + i2);
    float s1 = 0.f, s2 = 0.f;
    float4 c1 = make_float4(0.f, 0.f, 0.f, 0.f);
    float4 c2 = make_float4(0.f, 0.f, 0.f, 0.f);
    int e = g_off[w], e1 = g_off[w + 1];
    float4 xa1, xa2, xb1, xb2;
    if (e < e1) {
        const __half* hp = hs16 + (size_t)g_ssrc[e] * 256;
        xa1 = ldh4(hp + i1); xa2 = ldh4(hp + i2);
    }
    if (e + 1 < e1) {
        const __half* hp = hs16 + (size_t)g_ssrc[e + 1] * 256;
        xb1 = ldh4(hp + i1); xb2 = ldh4(hp + i2);
    }
    while (e < e1) {
        float4 u1 = xa1, u2 = xa2, v1 = xb1, v2 = xb2;
        bool two = (e + 1 < e1);
        if (e + 2 < e1) {
            const __half* hp = hs16 + (size_t)g_ssrc[e + 2] * 256;
            xa1 = ldh4(hp + i1); xa2 = ldh4(hp + i2);
        }
        if (e + 3 < e1) {
            const __half* hp = hs16 + (size_t)g_ssrc[e + 3] * 256;
            xb1 = ldh4(hp + i1); xb2 = ldh4(hp + i2);
        }
        float pa1 = lrdot(u1, d1, a1), pa2 = lrdot(u2, d2, a2);
        float pb1 = 0.f, pb2 = 0.f;
        if (two) { pb1 = lrdot(v1, d1, a1); pb2 = lrdot(v2, d2, a2); }
#pragma unroll
        for (int o = 8; o; o >>= 1) {
            pa1 += __shfl_xor_sync(0xffffffffu, pa1, o);
            pa2 += __shfl_xor_sync(0xffffffffu, pa2, o);
            pb1 += __shfl_xor_sync(0xffffffffu, pb1, o);
            pb2 += __shfl_xor_sync(0xffffffffu, pb2, o);
        }
        float wa1 = __expf(pa1), wa2 = __expf(pa2);
        s1 += wa1; s2 += wa2;
        c1.x += wa1 * u1.x; c1.y += wa1 * u1.y; c1.z += wa1 * u1.z; c1.w += wa1 * u1.w;
        c2.x += wa2 * u2.x; c2.y += wa2 * u2.y; c2.z += wa2 * u2.z; c2.w += wa2 * u2.w;
        if (two) {
            float wb1 = __expf(pb1), wb2 = __expf(pb2);
            s1 += wb1; s2 += wb2;
            c1.x += wb1 * v1.x; c1.y += wb1 * v1.y; c1.z += wb1 * v1.z; c1.w += wb1 * v1.w;
            c2.x += wb2 * v2.x; c2.y += wb2 * v2.y; c2.z += wb2 * v2.z; c2.w += wb2 * v2.w;
        }
        e += 2;
    }
    float inv1 = (s1 > 0.f) ? 1.f / s1 : 0.f;
    float inv2 = (s2 > 0.f) ? 1.f / s2 : 0.f;
    const float* rp = resB + (size_t)w * resS;
    float4 r1 = *(const float4*)(rp + i1);
    float4 r2 = *(const float4*)(rp + i2);
    float o1[4], o2[4];
    o1[0] = c1.x * inv1 + r1.x; o1[1] = c1.y * inv1 + r1.y;
    o1[2] = c1.z * inv1 + r1.z; o1[3] = c1.w * inv1 + r1.w;
    o2[0] = c2.x * inv2 + r2.x; o2[1] = c2.y * inv2 + r2.y;
    o2[2] = c2.z * inv2 + r2.z; o2[3] = c2.w * inv2 + r2.w;
    size_t nb = (size_t)w * 256;
    if (xout) {
        *(float4*)(xout + nb + i1) = make_float4(o1[0], o1[1], o1[2], o1[3]);
        *(float4*)(xout + nb + i2) = make_float4(o2[0], o2[1], o2[2], o2[3]);
    }
    __half2* xh2 = (__half2*)(xh + nb);
#pragma unroll
    for (int j = 0; j < 2; j++) {
        xh2[(i1 >> 1) + j] = __floats2half2_rn(o1[2*j], o1[2*j+1]);
        xh2[(i2 >> 1) + j] = __floats2half2_rn(o2[2*j], o2[2*j+1]);
    }
}

__global__ void __launch_bounds__(256) gat_edge_d40(
    const float* __restrict__ hsB, int hsS,
    const float* __restrict__ hdB, int hdS,
    const float* __restrict__ attn,
    const float* __restrict__ resB, int resS,
    float* __restrict__ out, int N)
{
    int w = (blockIdx.x * blockDim.x + threadIdx.x) >> 5;
    if (w >= N) return;
    int lane = threadIdx.x & 31;
    int h = lane >> 3;
    int d0 = (lane & 7) * 5;
    int idx = h * 40 + d0;
    float a[5], dv[5];
    const float* hdp = hdB + (size_t)w * hdS + idx;
#pragma unroll
    for (int j = 0; j < 5; j++) { a[j] = attn[idx + j]; dv[j] = hdp[j]; }
    float s = 0.f;
    float acc[5] = {0.f, 0.f, 0.f, 0.f, 0.f};
    int e = g_off[w], e1 = g_off[w + 1];
    float pfa[5], pfb[5];
    if (e < e1) {
        const float* hp = hsB + (size_t)g_ssrc[e] * hsS + idx;
#pragma unroll
        for (int j = 0; j < 5; j++) pfa[j] = hp[j];
    }
    if (e + 1 < e1) {
        const float* hp = hsB + (size_t)g_ssrc[e + 1] * hsS + idx;
#pragma unroll
        for (int j = 0; j < 5; j++) pfb[j] = hp[j];
    }
    while (e < e1) {
        float ua[5], ub[5];
#pragma unroll
        for (int j = 0; j < 5; j++) { ua[j] = pfa[j]; ub[j] = pfb[j]; }
        bool two = (e + 1 < e1);
        if (e + 2 < e1) {
            const float* hp = hsB + (size_t)g_ssrc[e + 2] * hsS + idx;
#pragma unroll
            for (int j = 0; j < 5; j++) pfa[j] = hp[j];
        }
        if (e + 3 < e1) {
            const float* hp = hsB + (size_t)g_ssrc[e + 3] * hsS + idx;
#pragma unroll
            for (int j = 0; j < 5; j++) pfb[j] = hp[j];
        }
        float qa = 0.f, qb = 0.f;
#pragma unroll
        for (int j = 0; j < 5; j++) qa += lrelu(ua[j] + dv[j]) * a[j];
        if (two) {
#pragma unroll
            for (int j = 0; j < 5; j++) qb += lrelu(ub[j] + dv[j]) * a[j];
        }
#pragma unroll
        for (int o = 4; o; o >>= 1) {
            qa += __shfl_xor_sync(0xffffffffu, qa, o);
            qb += __shfl_xor_sync(0xffffffffu, qb, o);
        }
        float wa = __expf(qa);
        s += wa;
#pragma unroll
        for (int j = 0; j < 5; j++) acc[j] += wa * ua[j];
        if (two) {
            float wb = __expf(qb);
            s += wb;
#pragma unroll
            for (int j = 0; j < 5; j++) acc[j] += wb * ub[j];
        }
        e += 2;
    }
    float inv = (s > 0.f) ? 1.f / s : 0.f;
    const float* rp = resB + (size_t)w * resS + idx;
    float v[5];
#pragma unroll
    for (int j = 0; j < 5; j++) v[j] = acc[j] * inv + rp[j];
#pragma unroll
    for (int j = 0; j < 5; j++) {
        v[j] += __shfl_xor_sync(0xffffffffu, v[j], 8);
        v[j] += __shfl_xor_sync(0xffffffffu, v[j], 16);
    }
    if (lane < 8) {
#pragma unroll
        for (int j = 0; j < 5; j++) out[(size_t)w * 40 + d0 + j] = 0.25f * v[j];
    }
}

// ---------------- launch ----------------
#define SMEM_L0 (2 * 128 * 272 + 256 * 272)   // 139264
#define SMEM_L1 (2 * 128 * 272 + 256 * 528)   // 204800
#define SMEM_L2 (2 * 128 * 272 + 160 * 528)   // 154112

extern "C" void kernel_launch(void* const* d_in, const int* in_sizes, int n_in,
                              void* d_out, int out_size)
{
    const float* x0  = (const float*)d_in[0];
    const int*   src = (const int*)d_in[1];
    const int*   dst = (const int*)d_in[2];
    const float* ws0 = (const float*)d_in[3];
    const float* bs0 = (const float*)d_in[4];
    const float* wd0 = (const float*)d_in[5];
    const float* bd0 = (const float*)d_in[6];
    const float* at0 = (const float*)d_in[7];
    const float* wr0 = (const float*)d_in[8];
    const float* br0 = (const float*)d_in[9];
    const float* ws1 = (const float*)d_in[10];
    const float* bs1 = (const float*)d_in[11];
    const float* wd1 = (const float*)d_in[12];
    const float* bd1 = (const float*)d_in[13];
    const float* at1 = (const float*)d_in[14];
    const float* ws2 = (const float*)d_in[15];
    const float* bs2 = (const float*)d_in[16];
    const float* wd2 = (const float*)d_in[17];
    const float* bd2 = (const float*)d_in[18];
    const float* at2 = (const float*)d_in[19];
    const float* wr2 = (const float*)d_in[20];
    const float* br2 = (const float*)d_in[21];
    float* out = (float*)d_out;

    const int N = NN, E = EE;

    float *big0, *big1, *big2, *xA, *b0, *b1, *b2;
    __half *xh, *wh, *hs16;
    cudaGetSymbolAddress((void**)&big0, g_big0);
    cudaGetSymbolAddress((void**)&big1, g_big1);
    cudaGetSymbolAddress((void**)&big2, g_big2);
    cudaGetSymbolAddress((void**)&xA,   g_xA);
    cudaGetSymbolAddress((void**)&xh,   g_xh);
    cudaGetSymbolAddress((void**)&wh,   g_wh);
    cudaGetSymbolAddress((void**)&hs16, g_hs16);
    cudaGetSymbolAddress((void**)&b0,   g_b0);
    cudaGetSymbolAddress((void**)&b1,   g_b1);
    cudaGetSymbolAddress((void**)&b2,   g_b2);

    cudaFuncSetAttribute(gemm_pers<8,128>, cudaFuncAttributeMaxDynamicSharedMemorySize, SMEM_L0);
    cudaFuncSetAttribute(gemm_pers<8,256>, cudaFuncAttributeMaxDynamicSharedMemorySize, SMEM_L1);
    cudaFuncSetAttribute(gemm_pers<5,256>, cudaFuncAttributeMaxDynamicSharedMemorySize, SMEM_L2);

    const int ewarps = (N * 32 + 255) / 256;
    const int hblk = (N * 64 + 255) / 256;

    // ---- prep + fused layer0 GEMM ----
    k_bias<<<(1760 + 255) / 256, 256>>>(bs0, bd0, br0, bs1, bd1, bs2, bd2, br2);
    k_xcvt<<<(N * 128 + 255) / 256, 256>>>(x0, xh, N * 128);
    k_wcvt<<<(128 * 256 + 255) / 256, 256>>>(ws0, 128, 256, WOFF_L0);
    k_wcvt<<<(128 * 256 + 255) / 256, 256>>>(wd0, 128, 256, WOFF_L0 + 256 * 128);
    k_wcvt<<<(128 * 256 + 255) / 256, 256>>>(wr0, 128, 256, WOFF_L0 + 512 * 128);
    gemm_pers<8,128><<<dim3(49, 3), 512, SMEM_L0>>>(xh, wh, WOFF_L0, b0, big0, N, 768);

    // ---- CSR by dst ----
    k_zero<<<(N + 255) / 256, 256>>>(N);
    k_hist<<<(E + 255) / 256, 256>>>(dst, E);
    int NB = (N + 1023) / 1024;
    k_scan_reduce<<<NB, 1024>>>(N);
    k_scan_bsum<<<1, 1>>>(NB, N, E);
    k_scan_final<<<NB, 1024>>>(N);
    k_scatter<<<(E + 255) / 256, 256>>>(src, dst, E);

    k_hcvt<<<hblk, 256>>>(big0, 768, hs16, N);
    gat_edge_d64<<<ewarps, 256>>>(hs16, big0 + 256, 768, at0,
                                  big0 + 512, 768, xA, xh, N);

    // ---- layer 1: fused hs|hd, identity residual (xA) ----
    k_wcvt<<<(256 * 256 + 255) / 256, 256>>>(ws1, 256, 256, WOFF_L1);
    k_wcvt<<<(256 * 256 + 255) / 256, 256>>>(wd1, 256, 256, WOFF_L1 + 256 * 256);
    gemm_pers<8,256><<<dim3(74, 2), 512, SMEM_L1>>>(xh, wh, WOFF_L1, b1, big1, N, 512);
    k_hcvt<<<hblk, 256>>>(big1, 512, hs16, N);
    gat_edge_d64<<<ewarps, 256>>>(hs16, big1 + 256, 512, at1,
                                  xA, 256, nullptr, xh, N);

    // ---- layer 2: fused hs|hd|res (BN=160), fused head-mean -> out ----
    k_wcvt<<<(256 * 160 + 255) / 256, 256>>>(ws2, 256, 160, WOFF_L2);
    k_wcvt<<<(256 * 160 + 255) / 256, 256>>>(wd2, 256, 160, WOFF_L2 + 160 * 256);
    k_wcvt<<<(256 * 160 + 255) / 256, 256>>>(wr2, 256, 160, WOFF_L2 + 320 * 256);
    gemm_pers<5,256><<<dim3(49, 3), 512, SMEM_L2>>>(xh, wh, WOFF_L2, b2, big2, N, 480);
    gat_edge_d40<<<ewarps, 256>>>(big2, 480, big2 + 160, 480, at2,
                                  big2 + 320, 480, out, N);
}

// round 15
// speedup vs baseline: 1.2191x; 1.1679x over previous
#include <cuda_runtime.h>
#include <cuda_fp16.h>
#include <math.h>
#include <stdint.h>

// ---------------- problem constants ----------------
#define NN 50000
#define EE 400000
#define MBNUM ((NN + 127) / 128)   // 391 M-blocks

// fused weight buffer offsets (elements), layout [NCtot][K] per layer
#define WOFF_L0 0                       // [768][128]
#define WOFF_L1 (WOFF_L0 + 768*128)     // [512][256]
#define WOFF_L2 (WOFF_L1 + 512*256)     // [480][256]
#define WTOT    (WOFF_L2 + 480*256)     // 352256

// ---------------- scratch (static device globals; 16B-aligned) ----------------
__device__ float g_big0[NN * 768];   // layer0: hs|hd|res
__device__ float g_big1[NN * 512];   // layer1: hs|hd
__device__ float g_big2[NN * 480];   // layer2: hs|hd|res
__device__ float g_xA[NN * 256];
__device__ __align__(256) __half g_xh[NN * 256];
__device__ __align__(256) __half g_wh[WTOT];
__device__ float g_b0[768];
__device__ float g_b1[512];
__device__ float g_b2[480];
__device__ int   g_deg[NN];
__device__ int   g_cur[NN];
__device__ int   g_off[NN + 1];
__device__ int   g_ssrc[EE];
__device__ int   g_bsum[64];

// ---------------- helpers (all proven) ----------------
__device__ __forceinline__ uint32_t smem_to_u32(const void* p) {
    uint32_t a;
    asm("{ .reg .u64 t; cvta.to.shared.u64 t, %1; cvt.u32.u64 %0, t; }" : "=r"(a) : "l"(p));
    return a;
}
__device__ __forceinline__ void cp16(uint32_t saddr, const void* gaddr, int sz) {
    asm volatile("cp.async.cg.shared.global [%0], [%1], 16, %2;\n"
                 :: "r"(saddr), "l"(gaddr), "r"(sz));
}
__device__ __forceinline__ void cp_commit() {
    asm volatile("cp.async.commit_group;\n" ::: "memory");
}
template<int N> __device__ __forceinline__ void cp_wait() {
    asm volatile("cp.async.wait_group %0;\n" :: "n"(N) : "memory");
}
__device__ __forceinline__ void ldsm4(uint32_t* r, uint32_t addr) {
    asm volatile("ldmatrix.sync.aligned.m8n8.x4.shared.b16 {%0,%1,%2,%3}, [%4];"
                 : "=r"(r[0]), "=r"(r[1]), "=r"(r[2]), "=r"(r[3]) : "r"(addr));
}
__device__ __forceinline__ void ldsm2(uint32_t* r, uint32_t addr) {
    asm volatile("ldmatrix.sync.aligned.m8n8.x2.shared.b16 {%0,%1}, [%2];"
                 : "=r"(r[0]), "=r"(r[1]) : "r"(addr));
}
__device__ __forceinline__ void mma_f16(float* c, const uint32_t* a, uint32_t b0, uint32_t b1) {
    asm volatile(
        "mma.sync.aligned.m16n8k16.row.col.f32.f16.f16.f32 "
        "{%0,%1,%2,%3}, {%4,%5,%6,%7}, {%8,%9}, {%0,%1,%2,%3};\n"
        : "+f"(c[0]), "+f"(c[1]), "+f"(c[2]), "+f"(c[3])
        : "r"(a[0]), "r"(a[1]), "r"(a[2]), "r"(a[3]), "r"(b0), "r"(b1));
}

// ---------------- CSR build ----------------
__global__ void k_hist(const int* __restrict__ dst, int E) {
    int i = blockIdx.x * 256 + threadIdx.x;
    if (i < E) atomicAdd(&g_deg[dst[i]], 1);
}
__global__ void k_scan_reduce(int n) {
    __shared__ int sm[1024];
    int tid = threadIdx.x;
    int i = blockIdx.x * 1024 + tid;
    sm[tid] = (i < n) ? g_deg[i] : 0;
    __syncthreads();
    for (int st = 512; st > 0; st >>= 1) {
        if (tid < st) sm[tid] += sm[tid + st];
        __syncthreads();
    }
    if (tid == 0) g_bsum[blockIdx.x] = sm[0];
}
__global__ void k_scan_bsum(int nb, int n, int E) {
    int run = 0;
    for (int b = 0; b < nb; b++) { int t = g_bsum[b]; g_bsum[b] = run; run += t; }
    g_off[n] = E;
}
__global__ void k_scan_final(int n) {
    __shared__ int sm[1024];
    int tid = threadIdx.x;
    int i = blockIdx.x * 1024 + tid;
    int v = (i < n) ? g_deg[i] : 0;
    sm[tid] = v;
    __syncthreads();
    for (int st = 1; st < 1024; st <<= 1) {
        int t = (tid >= st) ? sm[tid - st] : 0;
        __syncthreads();
        sm[tid] += t;
        __syncthreads();
    }
    if (i < n) g_off[i] = g_bsum[blockIdx.x] + sm[tid] - v;
}
__global__ void k_scatter(const int* __restrict__ src, const int* __restrict__ dst, int E) {
    int i = blockIdx.x * 256 + threadIdx.x;
    if (i < E) {
        int d = dst[i];
        int p = g_off[d] + atomicAdd(&g_cur[d], 1);
        g_ssrc[p] = src[i];
    }
}

// ---------------- fused prep: all 8 weight transposes + bias concat + deg/cur zero ----------------
#define PREP_BIAS  WTOT                    // 352256
#define PREP_ZERO  (PREP_BIAS + 1760)      // 354016
#define PREP_TOTAL (PREP_ZERO + 2 * NN)    // 454016

__global__ void k_prep(
    const float* __restrict__ ws0, const float* __restrict__ wd0, const float* __restrict__ wr0,
    const float* __restrict__ ws1, const float* __restrict__ wd1,
    const float* __restrict__ ws2, const float* __restrict__ wd2, const float* __restrict__ wr2,
    const float* __restrict__ bs0, const float* __restrict__ bd0, const float* __restrict__ br0,
    const float* __restrict__ bs1, const float* __restrict__ bd1,
    const float* __restrict__ bs2, const float* __restrict__ bd2, const float* __restrict__ br2)
{
    int i = blockIdx.x * 256 + threadIdx.x;
    if (i < WTOT) {
        const float* W; int kshift, NC, base;
        if (i < 98304) {                       // L0: 3 x [256][128]
            int seg = i >> 15; base = seg << 15;
            W = (seg == 0) ? ws0 : (seg == 1) ? wd0 : wr0;
            kshift = 7; NC = 256;
        } else if (i < 229376) {               // L1: 2 x [256][256]
            int j = i - 98304; int seg = j >> 16; base = 98304 + (seg << 16);
            W = seg ? wd1 : ws1;
            kshift = 8; NC = 256;
        } else {                               // L2: 3 x [160][256]
            int j = i - 229376; int seg = j / 40960; base = 229376 + seg * 40960;
            W = (seg == 0) ? ws2 : (seg == 1) ? wd2 : wr2;
            kshift = 8; NC = 160;
        }
        int local = i - base;
        int n = local >> kshift;
        int k = local & ((1 << kshift) - 1);
        g_wh[i] = __float2half(W[(size_t)k * NC + n]);
    } else if (i < PREP_ZERO) {
        int j = i - PREP_BIAS;
        if      (j < 256)  g_b0[j]        = bs0[j];
        else if (j < 512)  g_b0[j]        = bd0[j - 256];
        else if (j < 768)  g_b0[j]        = br0[j - 512];
        else if (j < 1024) g_b1[j - 768]  = bs1[j - 768];
        else if (j < 1280) g_b1[j - 768]  = bd1[j - 1024];
        else if (j < 1440) g_b2[j - 1280] = bs2[j - 1280];
        else if (j < 1600) g_b2[j - 1280] = bd2[j - 1440];
        else               g_b2[j - 1280] = br2[j - 1600];
    } else if (i < PREP_TOTAL) {
        int j = i - PREP_ZERO;
        if (j < NN) g_deg[j] = 0; else g_cur[j - NN] = 0;
    }
}

__global__ void k_xcvt(const float* __restrict__ X, __half* __restrict__ xh, int n)
{
    int i = blockIdx.x * 256 + threadIdx.x;
    if (i < n) xh[i] = __float2half(X[i]);
}

// ---------------- persistent fp16 GEMM (round-12 version, untouched) ----------------
template<int NFRAG, int KK>
__global__ void __launch_bounds__(512, 1) gemm_pers(
    const __half* __restrict__ A,
    const __half* __restrict__ WBase, int woff,
    const float* __restrict__ bias, float* __restrict__ C,
    int M, int NC)
{
    extern __shared__ char smem[];
    constexpr int BN  = NFRAG * 32;
    constexpr int BK  = 128;
    constexpr int KT  = KK / BK;
    constexpr int ARB = BK * 2 + 16;      // 272
    constexpr int BRB = KK * 2 + 16;      // 272 or 528
    constexpr int szA = 128 * ARB;
    constexpr int NP  = NFRAG / 2;

    const uint32_t sb = smem_to_u32(smem);
    const uint32_t sBp = sb + 2 * szA;
    const int tid  = threadIdx.x;
    const int lane = tid & 31;
    const int wid  = tid >> 5;
    const int wr   = (wid & 3) * 32;
    const int wc   = (wid >> 2) * (NFRAG * 8);
    const int bn   = blockIdx.y * BN;
    const int g    = lane >> 2;
    const int tg   = lane & 3;
    const int m8   = lane >> 3;
    const int r8   = lane & 7;
    const int aRow = (m8 & 1) * 8 + r8;
    const int aK   = (m8 >> 1) * 16;
    const int bRow = (m8 >> 1) * 8 + r8;
    const int bK   = (m8 & 1) * 16;
    const __half* __restrict__ B = WBase + woff;

    for (int i = tid; i < BN * (KK / 8); i += 512) {
        int row = i / (KK / 8), c = i % (KK / 8);
        cp16(sBp + row * BRB + c * 16, B + (size_t)(bn + row) * KK + c * 8, 16);
    }
    auto stageA = [&](uint32_t buf, int mb, int kt) {
        int bm = mb * 128;
        for (int i = tid; i < 2048; i += 512) {
            int row = i >> 4, c = i & 15;
            uint32_t sa = buf + row * ARB + c * 16;
            size_t go = (size_t)(bm + row) * KK + kt * BK + c * 8;
            cp16(sa, A + go, (bm + row < M) ? 16 : 0);
        }
    };
    stageA(sb, blockIdx.x, 0);
    cp_commit();

    int nM = 0;
    for (int m = blockIdx.x; m < MBNUM; m += gridDim.x) nM++;
    const int nT = nM * KT;

    float acc[2][NFRAG][4];
#pragma unroll
    for (int i = 0; i < 2; i++)
#pragma unroll
        for (int j = 0; j < NFRAG; j++)
#pragma unroll
            for (int k = 0; k < 4; k++) acc[i][j][k] = 0.f;

    for (int t = 0; t < nT; t++) {
        int nxt = t + 1;
        if (nxt < nT) {
            int mb = blockIdx.x + (nxt / KT) * gridDim.x;
            stageA(sb + (nxt & 1) * szA, mb, nxt % KT);
            cp_commit();
            cp_wait<1>();
        } else {
            cp_wait<0>();
        }
        __syncthreads();

        const uint32_t sA = sb + (t & 1) * szA;
        const int ktile = t % KT;
#pragma unroll
        for (int kc = 0; kc < BK / 16; kc++) {
            const int kbA = kc * 32;
            const int kbB = ktile * (BK * 2) + kc * 32;
            uint32_t a[2][4];
#pragma unroll
            for (int fr = 0; fr < 2; fr++) {
                uint32_t off = (uint32_t)(wr + fr * 16 + aRow) * ARB + kbA + aK;
                ldsm4(a[fr], sA + off);
            }
            uint32_t b[NFRAG][2];
#pragma unroll
            for (int p = 0; p < NP; p++) {
                uint32_t off = (uint32_t)(wc + p * 16 + bRow) * BRB + kbB + bK;
                uint32_t tt[4];
                ldsm4(tt, sBp + off);
                b[2*p][0] = tt[0]; b[2*p][1] = tt[1]; b[2*p+1][0] = tt[2]; b[2*p+1][1] = tt[3];
            }
            if (NFRAG & 1) {
                uint32_t off = (uint32_t)(wc + (NFRAG - 1) * 8 + r8) * BRB + kbB + (m8 & 1) * 16;
                uint32_t tt[2];
                ldsm2(tt, sBp + off);
                b[NFRAG-1][0] = tt[0]; b[NFRAG-1][1] = tt[1];
            }
#pragma unroll
            for (int fc = 0; fc < NFRAG; fc++)
#pragma unroll
                for (int fr = 0; fr < 2; fr++)
                    mma_f16(acc[fr][fc], a[fr], b[fc][0], b[fc][1]);
        }

        if (ktile == KT - 1) {
            int bm = (blockIdx.x + (t / KT) * gridDim.x) * 128;
#pragma unroll
            for (int fr = 0; fr < 2; fr++) {
                int r0 = bm + wr + fr * 16 + g;
#pragma unroll
                for (int fc = 0; fc < NFRAG; fc++) {
                    int c = bn + wc + fc * 8 + tg * 2;
                    float2 bb = *(const float2*)(bias + c);
                    if (r0 < M) {
                        float2 o = make_float2(acc[fr][fc][0] + bb.x, acc[fr][fc][1] + bb.y);
                        *(float2*)(C + (size_t)r0 * NC + c) = o;
                    }
                    if (r0 + 8 < M) {
                        float2 o = make_float2(acc[fr][fc][2] + bb.x, acc[fr][fc][3] + bb.y);
                        *(float2*)(C + (size_t)(r0 + 8) * NC + c) = o;
                    }
#pragma unroll
                    for (int k = 0; k < 4; k++) acc[fr][fc][k] = 0.f;
                }
            }
        }
        __syncthreads();
    }
}

// ---------------- edge kernels ----------------
__device__ __forceinline__ float lrelu(float t) { return t > 0.f ? t : 0.2f * t; }
__device__ __forceinline__ float lrdot(float4 h, float4 d, float4 a) {
    return lrelu(h.x + d.x) * a.x + lrelu(h.y + d.y) * a.y +
           lrelu(h.z + d.z) * a.z + lrelu(h.w + d.w) * a.w;
}

// d64: lane -> (head = lane>>3, dims (lane&7)*8). 8-lane reduction (3 shuffles).
__global__ void __launch_bounds__(256) gat_edge_d64(
    const float* __restrict__ hsB, int hsS,
    const float* __restrict__ hdB, int hdS,
    const float* __restrict__ attn,
    const float* __restrict__ resB, int resS,
    float* __restrict__ xout, __half* __restrict__ xh, int N)
{
    int w = (blockIdx.x * blockDim.x + threadIdx.x) >> 5;
    if (w >= N) return;
    int lane = threadIdx.x & 31;
    int idx = (lane >> 3) * 64 + (lane & 7) * 8;   // 8 dims of one head
    float4 aA = *(const float4*)(attn + idx);
    float4 aB = *(const float4*)(attn + idx + 4);
    const float* hdp = hdB + (size_t)w * hdS + idx;
    float4 dA = *(const float4*)(hdp);
    float4 dB = *(const float4*)(hdp + 4);
    float s = 0.f;
    float4 cA = make_float4(0.f, 0.f, 0.f, 0.f), cB = cA;
    int e = g_off[w], e1 = g_off[w + 1];
    float4 xaA, xaB, xbA, xbB;
    if (e < e1) {
        const float* hp = hsB + (size_t)g_ssrc[e] * hsS + idx;
        xaA = *(const float4*)hp; xaB = *(const float4*)(hp + 4);
    }
    if (e + 1 < e1) {
        const float* hp = hsB + (size_t)g_ssrc[e + 1] * hsS + idx;
        xbA = *(const float4*)hp; xbB = *(const float4*)(hp + 4);
    }
    while (e < e1) {
        float4 uA = xaA, uB = xaB, vA = xbA, vB = xbB;
        bool two = (e + 1 < e1);
        if (e + 2 < e1) {
            const float* hp = hsB + (size_t)g_ssrc[e + 2] * hsS + idx;
            xaA = *(const float4*)hp; xaB = *(const float4*)(hp + 4);
        }
        if (e + 3 < e1) {
            const float* hp = hsB + (size_t)g_ssrc[e + 3] * hsS + idx;
            xbA = *(const float4*)hp; xbB = *(const float4*)(hp + 4);
        }
        float pa = lrdot(uA, dA, aA) + lrdot(uB, dB, aB);
        float pb = two ? (lrdot(vA, dA, aA) + lrdot(vB, dB, aB)) : 0.f;
#pragma unroll
        for (int o = 4; o; o >>= 1) {
            pa += __shfl_xor_sync(0xffffffffu, pa, o);
            pb += __shfl_xor_sync(0xffffffffu, pb, o);
        }
        float wa = __expf(pa);
        s += wa;
        cA.x += wa * uA.x; cA.y += wa * uA.y; cA.z += wa * uA.z; cA.w += wa * uA.w;
        cB.x += wa * uB.x; cB.y += wa * uB.y; cB.z += wa * uB.z; cB.w += wa * uB.w;
        if (two) {
            float wb = __expf(pb);
            s += wb;
            cA.x += wb * vA.x; cA.y += wb * vA.y; cA.z += wb * vA.z; cA.w += wb * vA.w;
            cB.x += wb * vB.x; cB.y += wb * vB.y; cB.z += wb * vB.z; cB.w += wb * vB.w;
        }
        e += 2;
    }
    float inv = (s > 0.f) ? 1.f / s : 0.f;
    const float* rp = resB + (size_t)w * resS + idx;
    float4 rA = *(const float4*)rp;
    float4 rB = *(const float4*)(rp + 4);
    float4 oA, oB;
    oA.x = cA.x * inv + rA.x; oA.y = cA.y * inv + rA.y;
    oA.z = cA.z * inv + rA.z; oA.w = cA.w * inv + rA.w;
    oB.x = cB.x * inv + rB.x; oB.y = cB.y * inv + rB.y;
    oB.z = cB.z * inv + rB.z; oB.w = cB.w * inv + rB.w;
    size_t nb = (size_t)w * 256;
    if (xout) {
        *(float4*)(xout + nb + idx) = oA;
        *(float4*)(xout + nb + idx + 4) = oB;
    }
    uint4 hv;
    __half2 h0 = __floats2half2_rn(oA.x, oA.y);
    __half2 h1 = __floats2half2_rn(oA.z, oA.w);
    __half2 h2 = __floats2half2_rn(oB.x, oB.y);
    __half2 h3 = __floats2half2_rn(oB.z, oB.w);
    hv.x = *(uint32_t*)&h0; hv.y = *(uint32_t*)&h1;
    hv.z = *(uint32_t*)&h2; hv.w = *(uint32_t*)&h3;
    *(uint4*)(xh + nb + idx) = hv;
}

__global__ void __launch_bounds__(256) gat_edge_d40(
    const float* __restrict__ hsB, int hsS,
    const float* __restrict__ hdB, int hdS,
    const float* __restrict__ attn,
    const float* __restrict__ resB, int resS,
    float* __restrict__ out, int N)
{
    int w = (blockIdx.x * blockDim.x + threadIdx.x) >> 5;
    if (w >= N) return;
    int lane = threadIdx.x & 31;
    int h = lane >> 3;
    int d0 = (lane & 7) * 5;
    int idx = h * 40 + d0;
    float a[5], dv[5];
    const float* hdp = hdB + (size_t)w * hdS + idx;
#pragma unroll
    for (int j = 0; j < 5; j++) { a[j] = attn[idx + j]; dv[j] = hdp[j]; }
    float s = 0.f;
    float acc[5] = {0.f, 0.f, 0.f, 0.f, 0.f};
    int e = g_off[w], e1 = g_off[w + 1];
    float pfa[5], pfb[5];
    if (e < e1) {
        const float* hp = hsB + (size_t)g_ssrc[e] * hsS + idx;
#pragma unroll
        for (int j = 0; j < 5; j++) pfa[j] = hp[j];
    }
    if (e + 1 < e1) {
        const float* hp = hsB + (size_t)g_ssrc[e + 1] * hsS + idx;
#pragma unroll
        for (int j = 0; j < 5; j++) pfb[j] = hp[j];
    }
    while (e < e1) {
        float ua[5], ub[5];
#pragma unroll
        for (int j = 0; j < 5; j++) { ua[j] = pfa[j]; ub[j] = pfb[j]; }
        bool two = (e + 1 < e1);
        if (e + 2 < e1) {
            const float* hp = hsB + (size_t)g_ssrc[e + 2] * hsS + idx;
#pragma unroll
            for (int j = 0; j < 5; j++) pfa[j] = hp[j];
        }
        if (e + 3 < e1) {
            const float* hp = hsB + (size_t)g_ssrc[e + 3] * hsS + idx;
#pragma unroll
            for (int j = 0; j < 5; j++) pfb[j] = hp[j];
        }
        float qa = 0.f, qb = 0.f;
#pragma unroll
        for (int j = 0; j < 5; j++) qa += lrelu(ua[j] + dv[j]) * a[j];
        if (two) {
#pragma unroll
            for (int j = 0; j < 5; j++) qb += lrelu(ub[j] + dv[j]) * a[j];
        }
#pragma unroll
        for (int o = 4; o; o >>= 1) {
            qa += __shfl_xor_sync(0xffffffffu, qa, o);
            qb += __shfl_xor_sync(0xffffffffu, qb, o);
        }
        float wa = __expf(qa);
        s += wa;
#pragma unroll
        for (int j = 0; j < 5; j++) acc[j] += wa * ua[j];
        if (two) {
            float wb = __expf(qb);
            s += wb;
#pragma unroll
            for (int j = 0; j < 5; j++) acc[j] += wb * ub[j];
        }
        e += 2;
    }
    float inv = (s > 0.f) ? 1.f / s : 0.f;
    const float* rp = resB + (size_t)w * resS + idx;
    float v[5];
#pragma unroll
    for (int j = 0; j < 5; j++) v[j] = acc[j] * inv + rp[j];
#pragma unroll
    for (int j = 0; j < 5; j++) {
        v[j] += __shfl_xor_sync(0xffffffffu, v[j], 8);
        v[j] += __shfl_xor_sync(0xffffffffu, v[j], 16);
    }
    if (lane < 8) {
#pragma unroll
        for (int j = 0; j < 5; j++) out[(size_t)w * 40 + d0 + j] = 0.25f * v[j];
    }
}

// ---------------- launch ----------------
#define SMEM_L0 (2 * 128 * 272 + 256 * 272)   // 139264
#define SMEM_L1 (2 * 128 * 272 + 256 * 528)   // 204800
#define SMEM_L2 (2 * 128 * 272 + 160 * 528)   // 154112

extern "C" void kernel_launch(void* const* d_in, const int* in_sizes, int n_in,
                              void* d_out, int out_size)
{
    const float* x0  = (const float*)d_in[0];
    const int*   src = (const int*)d_in[1];
    const int*   dst = (const int*)d_in[2];
    const float* ws0 = (const float*)d_in[3];
    const float* bs0 = (const float*)d_in[4];
    const float* wd0 = (const float*)d_in[5];
    const float* bd0 = (const float*)d_in[6];
    const float* at0 = (const float*)d_in[7];
    const float* wr0 = (const float*)d_in[8];
    const float* br0 = (const float*)d_in[9];
    const float* ws1 = (const float*)d_in[10];
    const float* bs1 = (const float*)d_in[11];
    const float* wd1 = (const float*)d_in[12];
    const float* bd1 = (const float*)d_in[13];
    const float* at1 = (const float*)d_in[14];
    const float* ws2 = (const float*)d_in[15];
    const float* bs2 = (const float*)d_in[16];
    const float* wd2 = (const float*)d_in[17];
    const float* bd2 = (const float*)d_in[18];
    const float* at2 = (const float*)d_in[19];
    const float* wr2 = (const float*)d_in[20];
    const float* br2 = (const float*)d_in[21];
    float* out = (float*)d_out;

    const int N = NN, E = EE;

    float *big0, *big1, *big2, *xA, *b0, *b1, *b2;
    __half *xh, *wh;
    cudaGetSymbolAddress((void**)&big0, g_big0);
    cudaGetSymbolAddress((void**)&big1, g_big1);
    cudaGetSymbolAddress((void**)&big2, g_big2);
    cudaGetSymbolAddress((void**)&xA,   g_xA);
    cudaGetSymbolAddress((void**)&xh,   g_xh);
    cudaGetSymbolAddress((void**)&wh,   g_wh);
    cudaGetSymbolAddress((void**)&b0,   g_b0);
    cudaGetSymbolAddress((void**)&b1,   g_b1);
    cudaGetSymbolAddress((void**)&b2,   g_b2);

    cudaFuncSetAttribute(gemm_pers<8,128>, cudaFuncAttributeMaxDynamicSharedMemorySize, SMEM_L0);
    cudaFuncSetAttribute(gemm_pers<8,256>, cudaFuncAttributeMaxDynamicSharedMemorySize, SMEM_L1);
    cudaFuncSetAttribute(gemm_pers<5,256>, cudaFuncAttributeMaxDynamicSharedMemorySize, SMEM_L2);

    const int ewarps = (N * 32 + 255) / 256;

    // ---- fused prep (1 launch) + x convert ----
    k_prep<<<(PREP_TOTAL + 255) / 256, 256>>>(ws0, wd0, wr0, ws1, wd1, ws2, wd2, wr2,
                                              bs0, bd0, br0, bs1, bd1, bs2, bd2, br2);
    k_xcvt<<<(N * 128 + 255) / 256, 256>>>(x0, xh, N * 128);

    // ---- layer 0 fused GEMM ----
    gemm_pers<8,128><<<dim3(49, 3), 512, SMEM_L0>>>(xh, wh, WOFF_L0, b0, big0, N, 768);

    // ---- CSR by dst ----
    k_hist<<<(E + 255) / 256, 256>>>(dst, E);
    int NB = (N + 1023) / 1024;
    k_scan_reduce<<<NB, 1024>>>(N);
    k_scan_bsum<<<1, 1>>>(NB, N, E);
    k_scan_final<<<NB, 1024>>>(N);
    k_scatter<<<(E + 255) / 256, 256>>>(src, dst, E);

    gat_edge_d64<<<ewarps, 256>>>(big0, 768, big0 + 256, 768, at0,
                                  big0 + 512, 768, xA, xh, N);

    // ---- layer 1: fused hs|hd, identity residual (xA) ----
    gemm_pers<8,256><<<dim3(74, 2), 512, SMEM_L1>>>(xh, wh, WOFF_L1, b1, big1, N, 512);
    gat_edge_d64<<<ewarps, 256>>>(big1, 512, big1 + 256, 512, at1,
                                  xA, 256, nullptr, xh, N);

    // ---- layer 2: fused hs|hd|res (BN=160), fused head-mean -> out ----
    gemm_pers<5,256><<<dim3(49, 3), 512, SMEM_L2>>>(xh, wh, WOFF_L2, b2, big2, N, 480);
    gat_edge_d40<<<ewarps, 256>>>(big2, 480, big2 + 160, 480, at2,
                                  big2 + 320, 480, out, N);
}

// round 17
// speedup vs baseline: 1.2576x; 1.0316x over previous
#include <cuda_runtime.h>
#include <cuda_fp16.h>
#include <math.h>
#include <stdint.h>

// ---------------- problem constants ----------------
#define NN 50000
#define EE 400000
#define MBNUM ((NN + 127) / 128)   // 391 M-blocks

// fused weight buffer offsets (elements), layout [NCtot][K] per layer
#define WOFF_L0 0                       // [768][128]
#define WOFF_L1 (WOFF_L0 + 768*128)     // [512][256]
#define WOFF_L2 (WOFF_L1 + 512*256)     // [480][256]
#define WTOT    (WOFF_L2 + 480*256)     // 352256

// ---------------- scratch (static device globals; 16B-aligned) ----------------
__device__ float g_big0[NN * 768];   // layer0: hs|hd|res
__device__ float g_big1[NN * 512];   // layer1: hs|hd
__device__ float g_big2[NN * 480];   // layer2: hs|hd|res
__device__ float g_xA[NN * 256];
__device__ __align__(256) __half g_xh[NN * 256];
__device__ __align__(256) __half g_wh[WTOT];
__device__ float g_b0[768];
__device__ float g_b1[512];
__device__ float g_b2[480];
__device__ int   g_deg[NN];
__device__ int   g_cur[NN];
__device__ int   g_off[NN];
__device__ int   g_ssrc[EE];
__device__ int   g_total;

// ---------------- helpers (all proven) ----------------
__device__ __forceinline__ uint32_t smem_to_u32(const void* p) {
    uint32_t a;
    asm("{ .reg .u64 t; cvta.to.shared.u64 t, %1; cvt.u32.u64 %0, t; }" : "=r"(a) : "l"(p));
    return a;
}
__device__ __forceinline__ void cp16(uint32_t saddr, const void* gaddr, int sz) {
    asm volatile("cp.async.cg.shared.global [%0], [%1], 16, %2;\n"
                 :: "r"(saddr), "l"(gaddr), "r"(sz));
}
__device__ __forceinline__ void cp_commit() {
    asm volatile("cp.async.commit_group;\n" ::: "memory");
}
template<int N> __device__ __forceinline__ void cp_wait() {
    asm volatile("cp.async.wait_group %0;\n" :: "n"(N) : "memory");
}
__device__ __forceinline__ void ldsm4(uint32_t* r, uint32_t addr) {
    asm volatile("ldmatrix.sync.aligned.m8n8.x4.shared.b16 {%0,%1,%2,%3}, [%4];"
                 : "=r"(r[0]), "=r"(r[1]), "=r"(r[2]), "=r"(r[3]) : "r"(addr));
}
__device__ __forceinline__ void ldsm2(uint32_t* r, uint32_t addr) {
    asm volatile("ldmatrix.sync.aligned.m8n8.x2.shared.b16 {%0,%1}, [%2];"
                 : "=r"(r[0]), "=r"(r[1]) : "r"(addr));
}
__device__ __forceinline__ void mma_f16(float* c, const uint32_t* a, uint32_t b0, uint32_t b1) {
    asm volatile(
        "mma.sync.aligned.m16n8k16.row.col.f32.f16.f16.f32 "
        "{%0,%1,%2,%3}, {%4,%5,%6,%7}, {%8,%9}, {%0,%1,%2,%3};\n"
        : "+f"(c[0]), "+f"(c[1]), "+f"(c[2]), "+f"(c[3])
        : "r"(a[0]), "r"(a[1]), "r"(a[2]), "r"(a[3]), "r"(b0), "r"(b1));
}

// ---------------- CSR build (scan-free) ----------------
__global__ void k_hist(const int* __restrict__ dst, int E) {
    int i = blockIdx.x * 256 + threadIdx.x;
    if (i < E) atomicAdd(&g_deg[dst[i]], 1);
}
// unordered segment offsets: off[i] = fetch-add(total, deg[i])
__global__ void k_off(int n) {
    int i = blockIdx.x * 256 + threadIdx.x;
    if (i < n) g_off[i] = atomicAdd(&g_total, g_deg[i]);
}
__global__ void k_scatter(const int* __restrict__ src, const int* __restrict__ dst, int E) {
    int i = blockIdx.x * 256 + threadIdx.x;
    if (i < E) {
        int d = dst[i];
        int p = g_off[d] + atomicAdd(&g_cur[d], 1);
        g_ssrc[p] = src[i];
    }
}

// ---------------- fused prep: weight transposes + bias concat + deg/cur/total zero ----------------
#define PREP_BIAS  WTOT                    // 352256
#define PREP_ZERO  (PREP_BIAS + 1760)      // 354016
#define PREP_TOTAL (PREP_ZERO + 2 * NN + 1)

__global__ void k_prep(
    const float* __restrict__ ws0, const float* __restrict__ wd0, const float* __restrict__ wr0,
    const float* __restrict__ ws1, const float* __restrict__ wd1,
    const float* __restrict__ ws2, const float* __restrict__ wd2, const float* __restrict__ wr2,
    const float* __restrict__ bs0, const float* __restrict__ bd0, const float* __restrict__ br0,
    const float* __restrict__ bs1, const float* __restrict__ bd1,
    const float* __restrict__ bs2, const float* __restrict__ bd2, const float* __restrict__ br2)
{
    int i = blockIdx.x * 256 + threadIdx.x;
    if (i < WTOT) {
        const float* W; int kshift, NC, base;
        if (i < 98304) {                       // L0: 3 x [256][128]
            int seg = i >> 15; base = seg << 15;
            W = (seg == 0) ? ws0 : (seg == 1) ? wd0 : wr0;
            kshift = 7; NC = 256;
        } else if (i < 229376) {               // L1: 2 x [256][256]
            int j = i - 98304; int seg = j >> 16; base = 98304 + (seg << 16);
            W = seg ? wd1 : ws1;
            kshift = 8; NC = 256;
        } else {                               // L2: 3 x [160][256]
            int j = i - 229376; int seg = j / 40960; base = 229376 + seg * 40960;
            W = (seg == 0) ? ws2 : (seg == 1) ? wd2 : wr2;
            kshift = 8; NC = 160;
        }
        int local = i - base;
        int n = local >> kshift;
        int k = local & ((1 << kshift) - 1);
        g_wh[i] = __float2half(W[(size_t)k * NC + n]);
    } else if (i < PREP_ZERO) {
        int j = i - PREP_BIAS;
        if      (j < 256)  g_b0[j]        = bs0[j];
        else if (j < 512)  g_b0[j]        = bd0[j - 256];
        else if (j < 768)  g_b0[j]        = br0[j - 512];
        else if (j < 1024) g_b1[j - 768]  = bs1[j - 768];
        else if (j < 1280) g_b1[j - 768]  = bd1[j - 1024];
        else if (j < 1440) g_b2[j - 1280] = bs2[j - 1280];
        else if (j < 1600) g_b2[j - 1280] = bd2[j - 1440];
        else               g_b2[j - 1280] = br2[j - 1600];
    } else if (i < PREP_TOTAL) {
        int j = i - PREP_ZERO;
        if      (j < NN)     g_deg[j] = 0;
        else if (j < 2 * NN) g_cur[j - NN] = 0;
        else                 g_total = 0;
    }
}

__global__ void k_xcvt(const float* __restrict__ X, __half* __restrict__ xh, int n)
{
    int i = blockIdx.x * 256 + threadIdx.x;
    if (i < n) xh[i] = __float2half(X[i]);
}

// ---------------- persistent fp16 GEMM (round-12 version, untouched) ----------------
template<int NFRAG, int KK>
__global__ void __launch_bounds__(512, 1) gemm_pers(
    const __half* __restrict__ A,
    const __half* __restrict__ WBase, int woff,
    const float* __restrict__ bias, float* __restrict__ C,
    int M, int NC)
{
    extern __shared__ char smem[];
    constexpr int BN  = NFRAG * 32;
    constexpr int BK  = 128;
    constexpr int KT  = KK / BK;
    constexpr int ARB = BK * 2 + 16;      // 272
    constexpr int BRB = KK * 2 + 16;      // 272 or 528
    constexpr int szA = 128 * ARB;
    constexpr int NP  = NFRAG / 2;

    const uint32_t sb = smem_to_u32(smem);
    const uint32_t sBp = sb + 2 * szA;
    const int tid  = threadIdx.x;
    const int lane = tid & 31;
    const int wid  = tid >> 5;
    const int wr   = (wid & 3) * 32;
    const int wc   = (wid >> 2) * (NFRAG * 8);
    const int bn   = blockIdx.y * BN;
    const int g    = lane >> 2;
    const int tg   = lane & 3;
    const int m8   = lane >> 3;
    const int r8   = lane & 7;
    const int aRow = (m8 & 1) * 8 + r8;
    const int aK   = (m8 >> 1) * 16;
    const int bRow = (m8 >> 1) * 8 + r8;
    const int bK   = (m8 & 1) * 16;
    const __half* __restrict__ B = WBase + woff;

    for (int i = tid; i < BN * (KK / 8); i += 512) {
        int row = i / (KK / 8), c = i % (KK / 8);
        cp16(sBp + row * BRB + c * 16, B + (size_t)(bn + row) * KK + c * 8, 16);
    }
    auto stageA = [&](uint32_t buf, int mb, int kt) {
        int bm = mb * 128;
        for (int i = tid; i < 2048; i += 512) {
            int row = i >> 4, c = i & 15;
            uint32_t sa = buf + row * ARB + c * 16;
            size_t go = (size_t)(bm + row) * KK + kt * BK + c * 8;
            cp16(sa, A + go, (bm + row < M) ? 16 : 0);
        }
    };
    stageA(sb, blockIdx.x, 0);
    cp_commit();

    int nM = 0;
    for (int m = blockIdx.x; m < MBNUM; m += gridDim.x) nM++;
    const int nT = nM * KT;

    float acc[2][NFRAG][4];
#pragma unroll
    for (int i = 0; i < 2; i++)
#pragma unroll
        for (int j = 0; j < NFRAG; j++)
#pragma unroll
            for (int k = 0; k < 4; k++) acc[i][j][k] = 0.f;

    for (int t = 0; t < nT; t++) {
        int nxt = t + 1;
        if (nxt < nT) {
            int mb = blockIdx.x + (nxt / KT) * gridDim.x;
            stageA(sb + (nxt & 1) * szA, mb, nxt % KT);
            cp_commit();
            cp_wait<1>();
        } else {
            cp_wait<0>();
        }
        __syncthreads();

        const uint32_t sA = sb + (t & 1) * szA;
        const int ktile = t % KT;
#pragma unroll
        for (int kc = 0; kc < BK / 16; kc++) {
            const int kbA = kc * 32;
            const int kbB = ktile * (BK * 2) + kc * 32;
            uint32_t a[2][4];
#pragma unroll
            for (int fr = 0; fr < 2; fr++) {
                uint32_t off = (uint32_t)(wr + fr * 16 + aRow) * ARB + kbA + aK;
                ldsm4(a[fr], sA + off);
            }
            uint32_t b[NFRAG][2];
#pragma unroll
            for (int p = 0; p < NP; p++) {
                uint32_t off = (uint32_t)(wc + p * 16 + bRow) * BRB + kbB + bK;
                uint32_t tt[4];
                ldsm4(tt, sBp + off);
                b[2*p][0] = tt[0]; b[2*p][1] = tt[1]; b[2*p+1][0] = tt[2]; b[2*p+1][1] = tt[3];
            }
            if (NFRAG & 1) {
                uint32_t off = (uint32_t)(wc + (NFRAG - 1) * 8 + r8) * BRB + kbB + (m8 & 1) * 16;
                uint32_t tt[2];
                ldsm2(tt, sBp + off);
                b[NFRAG-1][0] = tt[0]; b[NFRAG-1][1] = tt[1];
            }
#pragma unroll
            for (int fc = 0; fc < NFRAG; fc++)
#pragma unroll
                for (int fr = 0; fr < 2; fr++)
                    mma_f16(acc[fr][fc], a[fr], b[fc][0], b[fc][1]);
        }

        if (ktile == KT - 1) {
            int bm = (blockIdx.x + (t / KT) * gridDim.x) * 128;
#pragma unroll
            for (int fr = 0; fr < 2; fr++) {
                int r0 = bm + wr + fr * 16 + g;
#pragma unroll
                for (int fc = 0; fc < NFRAG; fc++) {
                    int c = bn + wc + fc * 8 + tg * 2;
                    float2 bb = *(const float2*)(bias + c);
                    if (r0 < M) {
                        float2 o = make_float2(acc[fr][fc][0] + bb.x, acc[fr][fc][1] + bb.y);
                        *(float2*)(C + (size_t)r0 * NC + c) = o;
                    }
                    if (r0 + 8 < M) {
                        float2 o = make_float2(acc[fr][fc][2] + bb.x, acc[fr][fc][3] + bb.y);
                        *(float2*)(C + (size_t)(r0 + 8) * NC + c) = o;
                    }
#pragma unroll
                    for (int k = 0; k < 4; k++) acc[fr][fc][k] = 0.f;
                }
            }
        }
        __syncthreads();
    }
}

// ---------------- edge kernels ----------------
__device__ __forceinline__ float lrelu(float t) { return t > 0.f ? t : 0.2f * t; }
__device__ __forceinline__ float lrdot(float4 h, float4 d, float4 a) {
    return lrelu(h.x + d.x) * a.x + lrelu(h.y + d.y) * a.y +
           lrelu(h.z + d.z) * a.z + lrelu(h.w + d.w) * a.w;
}

// d64: lane -> (head = lane>>3, dims (lane&7)*8). 8-lane reduction (3 shuffles).
__global__ void __launch_bounds__(256) gat_edge_d64(
    const float* __restrict__ hsB, int hsS,
    const float* __restrict__ hdB, int hdS,
    const float* __restrict__ attn,
    const float* __restrict__ resB, int resS,
    float* __restrict__ xout, __half* __restrict__ xh, int N)
{
    int w = (blockIdx.x * blockDim.x + threadIdx.x) >> 5;
    if (w >= N) return;
    int lane = threadIdx.x & 31;
    int idx = (lane >> 3) * 64 + (lane & 7) * 8;   // 8 dims of one head
    float4 aA = *(const float4*)(attn + idx);
    float4 aB = *(const float4*)(attn + idx + 4);
    const float* hdp = hdB + (size_t)w * hdS + idx;
    float4 dA = *(const float4*)(hdp);
    float4 dB = *(const float4*)(hdp + 4);
    float s = 0.f;
    float4 cA = make_float4(0.f, 0.f, 0.f, 0.f), cB = cA;
    int e = g_off[w], e1 = e + g_deg[w];
    float4 xaA, xaB, xbA, xbB;
    if (e < e1) {
        const float* hp = hsB + (size_t)g_ssrc[e] * hsS + idx;
        xaA = *(const float4*)hp; xaB = *(const float4*)(hp + 4);
    }
    if (e + 1 < e1) {
        const float* hp = hsB + (size_t)g_ssrc[e + 1] * hsS + idx;
        xbA = *(const float4*)hp; xbB = *(const float4*)(hp + 4);
    }
    while (e < e1) {
        float4 uA = xaA, uB = xaB, vA = xbA, vB = xbB;
        bool two = (e + 1 < e1);
        if (e + 2 < e1) {
            const float* hp = hsB + (size_t)g_ssrc[e + 2] * hsS + idx;
            xaA = *(const float4*)hp; xaB = *(const float4*)(hp + 4);
        }
        if (e + 3 < e1) {
            const float* hp = hsB + (size_t)g_ssrc[e + 3] * hsS + idx;
            xbA = *(const float4*)hp; xbB = *(const float4*)(hp + 4);
        }
        float pa = lrdot(uA, dA, aA) + lrdot(uB, dB, aB);
        float pb = two ? (lrdot(vA, dA, aA) + lrdot(vB, dB, aB)) : 0.f;
#pragma unroll
        for (int o = 4; o; o >>= 1) {
            pa += __shfl_xor_sync(0xffffffffu, pa, o);
            pb += __shfl_xor_sync(0xffffffffu, pb, o);
        }
        float wa = __expf(pa);
        s += wa;
        cA.x += wa * uA.x; cA.y += wa * uA.y; cA.z += wa * uA.z; cA.w += wa * uA.w;
        cB.x += wa * uB.x; cB.y += wa * uB.y; cB.z += wa * uB.z; cB.w += wa * uB.w;
        if (two) {
            float wb = __expf(pb);
            s += wb;
            cA.x += wb * vA.x; cA.y += wb * vA.y; cA.z += wb * vA.z; cA.w += wb * vA.w;
            cB.x += wb * vB.x; cB.y += wb * vB.y; cB.z += wb * vB.z; cB.w += wb * vB.w;
        }
        e += 2;
    }
    float inv = (s > 0.f) ? 1.f / s : 0.f;
    const float* rp = resB + (size_t)w * resS + idx;
    float4 rA = *(const float4*)rp;
    float4 rB = *(const float4*)(rp + 4);
    float4 oA, oB;
    oA.x = cA.x * inv + rA.x; oA.y = cA.y * inv + rA.y;
    oA.z = cA.z * inv + rA.z; oA.w = cA.w * inv + rA.w;
    oB.x = cB.x * inv + rB.x; oB.y = cB.y * inv + rB.y;
    oB.z = cB.z * inv + rB.z; oB.w = cB.w * inv + rB.w;
    size_t nb = (size_t)w * 256;
    if (xout) {
        *(float4*)(xout + nb + idx) = oA;
        *(float4*)(xout + nb + idx + 4) = oB;
    }
    uint4 hv;
    __half2 h0 = __floats2half2_rn(oA.x, oA.y);
    __half2 h1 = __floats2half2_rn(oA.z, oA.w);
    __half2 h2 = __floats2half2_rn(oB.x, oB.y);
    __half2 h3 = __floats2half2_rn(oB.z, oB.w);
    hv.x = *(uint32_t*)&h0; hv.y = *(uint32_t*)&h1;
    hv.z = *(uint32_t*)&h2; hv.w = *(uint32_t*)&h3;
    *(uint4*)(xh + nb + idx) = hv;
}

__global__ void __launch_bounds__(256) gat_edge_d40(
    const float* __restrict__ hsB, int hsS,
    const float* __restrict__ hdB, int hdS,
    const float* __restrict__ attn,
    const float* __restrict__ resB, int resS,
    float* __restrict__ out, int N)
{
    int w = (blockIdx.x * blockDim.x + threadIdx.x) >> 5;
    if (w >= N) return;
    int lane = threadIdx.x & 31;
    int h = lane >> 3;
    int d0 = (lane & 7) * 5;
    int idx = h * 40 + d0;
    float a[5], dv[5];
    const float* hdp = hdB + (size_t)w * hdS + idx;
#pragma unroll
    for (int j = 0; j < 5; j++) { a[j] = attn[idx + j]; dv[j] = hdp[j]; }
    float s = 0.f;
    float acc[5] = {0.f, 0.f, 0.f, 0.f, 0.f};
    int e = g_off[w], e1 = e + g_deg[w];
    float pfa[5], pfb[5];
    if (e < e1) {
        const float* hp = hsB + (size_t)g_ssrc[e] * hsS + idx;
#pragma unroll
        for (int j = 0; j < 5; j++) pfa[j] = hp[j];
    }
    if (e + 1 < e1) {
        const float* hp = hsB + (size_t)g_ssrc[e + 1] * hsS + idx;
#pragma unroll
        for (int j = 0; j < 5; j++) pfb[j] = hp[j];
    }
    while (e < e1) {
        float ua[5], ub[5];
#pragma unroll
        for (int j = 0; j < 5; j++) { ua[j] = pfa[j]; ub[j] = pfb[j]; }
        bool two = (e + 1 < e1);
        if (e + 2 < e1) {
            const float* hp = hsB + (size_t)g_ssrc[e + 2] * hsS + idx;
#pragma unroll
            for (int j = 0; j < 5; j++) pfa[j] = hp[j];
        }
        if (e + 3 < e1) {
            const float* hp = hsB + (size_t)g_ssrc[e + 3] * hsS + idx;
#pragma unroll
            for (int j = 0; j < 5; j++) pfb[j] = hp[j];
        }
        float qa = 0.f, qb = 0.f;
#pragma unroll
        for (int j = 0; j < 5; j++) qa += lrelu(ua[j] + dv[j]) * a[j];
        if (two) {
#pragma unroll
            for (int j = 0; j < 5; j++) qb += lrelu(ub[j] + dv[j]) * a[j];
        }
#pragma unroll
        for (int o = 4; o; o >>= 1) {
            qa += __shfl_xor_sync(0xffffffffu, qa, o);
            qb += __shfl_xor_sync(0xffffffffu, qb, o);
        }
        float wa = __expf(qa);
        s += wa;
#pragma unroll
        for (int j = 0; j < 5; j++) acc[j] += wa * ua[j];
        if (two) {
            float wb = __expf(qb);
            s += wb;
#pragma unroll
            for (int j = 0; j < 5; j++) acc[j] += wb * ub[j];
        }
        e += 2;
    }
    float inv = (s > 0.f) ? 1.f / s : 0.f;
    const float* rp = resB + (size_t)w * resS + idx;
    float v[5];
#pragma unroll
    for (int j = 0; j < 5; j++) v[j] = acc[j] * inv + rp[j];
#pragma unroll
    for (int j = 0; j < 5; j++) {
        v[j] += __shfl_xor_sync(0xffffffffu, v[j], 8);
        v[j] += __shfl_xor_sync(0xffffffffu, v[j], 16);
    }
    if (lane < 8) {
#pragma unroll
        for (int j = 0; j < 5; j++) out[(size_t)w * 40 + d0 + j] = 0.25f * v[j];
    }
}

// ---------------- launch ----------------
#define SMEM_L0 (2 * 128 * 272 + 256 * 272)   // 139264
#define SMEM_L1 (2 * 128 * 272 + 256 * 528)   // 204800
#define SMEM_L2 (2 * 128 * 272 + 160 * 528)   // 154112

extern "C" void kernel_launch(void* const* d_in, const int* in_sizes, int n_in,
                              void* d_out, int out_size)
{
    const float* x0  = (const float*)d_in[0];
    const int*   src = (const int*)d_in[1];
    const int*   dst = (const int*)d_in[2];
    const float* ws0 = (const float*)d_in[3];
    const float* bs0 = (const float*)d_in[4];
    const float* wd0 = (const float*)d_in[5];
    const float* bd0 = (const float*)d_in[6];
    const float* at0 = (const float*)d_in[7];
    const float* wr0 = (const float*)d_in[8];
    const float* br0 = (const float*)d_in[9];
    const float* ws1 = (const float*)d_in[10];
    const float* bs1 = (const float*)d_in[11];
    const float* wd1 = (const float*)d_in[12];
    const float* bd1 = (const float*)d_in[13];
    const float* at1 = (const float*)d_in[14];
    const float* ws2 = (const float*)d_in[15];
    const float* bs2 = (const float*)d_in[16];
    const float* wd2 = (const float*)d_in[17];
    const float* bd2 = (const float*)d_in[18];
    const float* at2 = (const float*)d_in[19];
    const float* wr2 = (const float*)d_in[20];
    const float* br2 = (const float*)d_in[21];
    float* out = (float*)d_out;

    const int N = NN, E = EE;

    float *big0, *big1, *big2, *xA, *b0, *b1, *b2;
    __half *xh, *wh;
    cudaGetSymbolAddress((void**)&big0, g_big0);
    cudaGetSymbolAddress((void**)&big1, g_big1);
    cudaGetSymbolAddress((void**)&big2, g_big2);
    cudaGetSymbolAddress((void**)&xA,   g_xA);
    cudaGetSymbolAddress((void**)&xh,   g_xh);
    cudaGetSymbolAddress((void**)&wh,   g_wh);
    cudaGetSymbolAddress((void**)&b0,   g_b0);
    cudaGetSymbolAddress((void**)&b1,   g_b1);
    cudaGetSymbolAddress((void**)&b2,   g_b2);

    cudaFuncSetAttribute(gemm_pers<8,128>, cudaFuncAttributeMaxDynamicSharedMemorySize, SMEM_L0);
    cudaFuncSetAttribute(gemm_pers<8,256>, cudaFuncAttributeMaxDynamicSharedMemorySize, SMEM_L1);
    cudaFuncSetAttribute(gemm_pers<5,256>, cudaFuncAttributeMaxDynamicSharedMemorySize, SMEM_L2);

    const int ewarps = (N * 32 + 255) / 256;

    // launches 1-5: prep, xcvt, hist, off, scatter  (GEMM L0 = #6 -> ncu window)
    k_prep<<<(PREP_TOTAL + 255) / 256, 256>>>(ws0, wd0, wr0, ws1, wd1, ws2, wd2, wr2,
                                              bs0, bd0, br0, bs1, bd1, bs2, bd2, br2);
    k_xcvt<<<(N * 128 + 255) / 256, 256>>>(x0, xh, N * 128);
    k_hist<<<(E + 255) / 256, 256>>>(dst, E);
    k_off<<<(N + 255) / 256, 256>>>(N);
    k_scatter<<<(E + 255) / 256, 256>>>(src, dst, E);

    // ---- layer 0: fused GEMM (#6) + edges ----
    gemm_pers<8,128><<<dim3(49, 3), 512, SMEM_L0>>>(xh, wh, WOFF_L0, b0, big0, N, 768);
    gat_edge_d64<<<ewarps, 256>>>(big0, 768, big0 + 256, 768, at0,
                                  big0 + 512, 768, xA, xh, N);

    // ---- layer 1: fused hs|hd, identity residual (xA) ----
    gemm_pers<8,256><<<dim3(74, 2), 512, SMEM_L1>>>(xh, wh, WOFF_L1, b1, big1, N, 512);
    gat_edge_d64<<<ewarps, 256>>>(big1, 512, big1 + 256, 512, at1,
                                  xA, 256, nullptr, xh, N);

    // ---- layer 2: fused hs|hd|res (BN=160), fused head-mean -> out ----
    gemm_pers<5,256><<<dim3(49, 3), 512, SMEM_L2>>>(xh, wh, WOFF_L2, b2, big2, N, 480);
    gat_edge_d40<<<ewarps, 256>>>(big2, 480, big2 + 160, 480, at2,
                                  big2 + 320, 480, out, N);
}